// round 7
// baseline (speedup 1.0000x reference)
#include <cuda_runtime.h>
#include <cuda_bf16.h>
#include <math.h>
#include <stdint.h>

// ---------------- problem constants ----------------
#define BSZ   2
#define LSEQ  4096
#define TTOT  8192          // BSZ*LSEQ
#define HIDD  768
#define IF    1536          // I
#define NST   128           // N
#define HH    24            // H
#define PP    64            // P
#define CSZ   256           // chunk size
#define CN    16            // LSEQ/CSZ
#define KC    4             // conv kernel
#define NPROJ 3352          // 2*(I+N)+H
#define XBCW  1792          // I+2N

// ---------------- scratch (static device globals; no allocs) ----------------
__device__ float g_zx[TTOT * NPROJ];               // in_proj output (z | xBC | dt)
__device__ float g_xc[TTOT * XBCW];                // conv+silu output
__device__ float g_dt[TTOT * HH];                  // softplus(dt+bias)
__device__ float g_ac[BSZ * HH * CN * CSZ];        // per-chunk inclusive cumsum of A*dt
__device__ float g_ls[BSZ * CN * HH * PP * NST];   // local chunk states
__device__ float g_ps[BSZ * CN * HH * PP * NST];   // prefix states entering chunk
__device__ float g_y [TTOT * IF];                  // y (tf32-rounded after gnorm)
__device__ float g_hsr [TTOT * HIDD];              // hs rounded to tf32
__device__ float g_inwT[NPROJ * HIDD];             // in_proj_w^T, tf32
__device__ float g_owT [HIDD * IF];                // out_proj_w^T, tf32

// ---------------- helpers ----------------
__device__ __forceinline__ float f2tf32(float x) {
    uint32_t r;
    asm("cvt.rna.tf32.f32 %0, %1;" : "=r"(r) : "f"(x));
    return __uint_as_float(r);
}
__device__ __forceinline__ uint32_t fu(float x) { return __float_as_uint(x); }

__device__ __forceinline__ void mma_tf32(float* c, uint32_t a0, uint32_t a1,
                                         uint32_t a2, uint32_t a3,
                                         uint32_t b0, uint32_t b1) {
    asm volatile(
        "mma.sync.aligned.m16n8k8.row.col.f32.tf32.tf32.f32 "
        "{%0,%1,%2,%3}, {%4,%5,%6,%7}, {%8,%9}, {%0,%1,%2,%3};\n"
        : "+f"(c[0]), "+f"(c[1]), "+f"(c[2]), "+f"(c[3])
        : "r"(a0), "r"(a1), "r"(a2), "r"(a3), "r"(b0), "r"(b1));
}
__device__ __forceinline__ void ldsm_x4(uint32_t addr, uint32_t& r0, uint32_t& r1,
                                        uint32_t& r2, uint32_t& r3) {
    asm volatile("ldmatrix.sync.aligned.m8n8.x4.shared.b16 {%0,%1,%2,%3}, [%4];"
                 : "=r"(r0), "=r"(r1), "=r"(r2), "=r"(r3) : "r"(addr));
}
__device__ __forceinline__ void cpasync16(uint32_t daddr, const void* gaddr, bool pred) {
    int sz = pred ? 16 : 0;
    asm volatile("cp.async.cg.shared.global [%0], [%1], 16, %2;"
                 :: "r"(daddr), "l"(gaddr), "r"(sz));
}
#define CP_COMMIT()  asm volatile("cp.async.commit_group;")
#define CP_WAIT2()   asm volatile("cp.async.wait_group 2;")

// ================= TF32 GEMM: ldmatrix + cp.async, BM=128 BN=64 BK=16, 4 stages =================
// C = A(MxK) @ Bt^T where Bt is [N][K] row-major, both pre-rounded tf32.
// 256 thr = 8 warps (warpM 2 x warpN 4), warp tile 64x16 -> acc 32 regs.
// Target: 3 CTAs/SM (24 warps) via __launch_bounds__(256,3).
#define GST 20                       // row stride (floats): 16 + 4 pad
#define STAGE_F ((128 + 64) * GST)   // floats per stage (A 128 rows + B 64 rows)
#define NSTAGE 4

__global__ __launch_bounds__(256, 3) void tf32gemm_ldsm_kernel(const float* __restrict__ A,
                                                               const float* __restrict__ Bt,
                                                               float* __restrict__ C,
                                                               int M, int N, int K) {
    extern __shared__ float sm[];
    const int tid = threadIdx.x;
    const int lane = tid & 31;
    const int warpId = tid >> 5;
    const int gid = lane >> 2, tig = lane & 3;
    const int warpM = warpId & 1;     // 2 x 64 rows
    const int warpN = warpId >> 1;    // 4 x 16 cols
    const int rowBase = blockIdx.y * 128;
    const int colBase = blockIdx.x * 64;
    const int nk = K >> 4;

    uint32_t smBase = (uint32_t)__cvta_generic_to_shared(sm);

    // cp.async A: row = tid>>1, two 16B chunks at (tid&1)*2
    const int apr = tid >> 1;
    const int apc = (tid & 1) * 2;
    const uint32_t aOff = (uint32_t)(apr * GST + apc * 4) * 4;
    // cp.async B: row = tid>>2 (0..63), one 16B chunk at tid&3
    const int bpr = tid >> 2;
    const int bpc = tid & 3;
    const int nB = colBase + bpr;
    const bool bOK = nB < N;
    const int nBc = bOK ? nB : 0;
    const uint32_t bOff = (uint32_t)(bpr * GST + bpc * 4) * 4;

    auto issue = [&](int kt, int stage) {
        int k0 = kt << 4;
        uint32_t sA = smBase + (uint32_t)(stage * STAGE_F) * 4 + aOff;
        uint32_t sB = smBase + (uint32_t)(stage * STAGE_F + 128 * GST) * 4 + bOff;
        const float* ga = &A[(size_t)(rowBase + apr) * K + k0 + apc * 4];
        const float* gb = &Bt[(size_t)nBc * K + k0 + bpc * 4];
        cpasync16(sA, ga, true);
        cpasync16(sA + 16, ga + 4, true);
        cpasync16(sB, gb, bOK);
        CP_COMMIT();
    };

    // ldmatrix per-lane offsets (floats within tile)
    const uint32_t aLaneOff = (uint32_t)((lane & 15) * GST + (lane >> 4) * 4);
    const uint32_t bLaneOff = (uint32_t)(((lane >> 4) * 8 + (lane & 7)) * GST + ((lane >> 3) & 1) * 4);

    float acc[4][2][4];
#pragma unroll
    for (int mt = 0; mt < 4; mt++)
#pragma unroll
        for (int nt = 0; nt < 2; nt++)
#pragma unroll
            for (int e = 0; e < 4; e++) acc[mt][nt][e] = 0.f;

    // prologue: fill 3 stages ahead
#pragma unroll
    for (int p = 0; p < NSTAGE - 1; p++)
        if (p < nk) issue(p, p);

    for (int kt = 0; kt < nk; kt++) {
        CP_WAIT2();
        __syncthreads();
        if (kt + NSTAGE - 1 < nk) issue(kt + NSTAGE - 1, (kt + NSTAGE - 1) % NSTAGE);

        int stage = kt % NSTAGE;
        uint32_t aBase = smBase + (uint32_t)(stage * STAGE_F) * 4;
        uint32_t bBase = smBase + (uint32_t)(stage * STAGE_F + 128 * GST) * 4;

#pragma unroll
        for (int ks = 0; ks < 2; ks++) {
            // B fragments: one ldsm_x4 covers this warp's 16 cols x 8 k
            uint32_t b0, b1, b2, b3;
            {
                uint32_t addr = bBase + ((uint32_t)((warpN * 16) * GST + ks * 8) + bLaneOff) * 4;
                ldsm_x4(addr, b0, b1, b2, b3);
            }
#pragma unroll
            for (int mt = 0; mt < 4; mt++) {
                uint32_t addr = aBase + ((uint32_t)((warpM * 64 + mt * 16) * GST + ks * 8) + aLaneOff) * 4;
                uint32_t a0, a1, a2, a3;
                ldsm_x4(addr, a0, a1, a2, a3);
                mma_tf32(acc[mt][0], a0, a1, a2, a3, b0, b1);
                mma_tf32(acc[mt][1], a0, a1, a2, a3, b2, b3);
            }
        }
    }

    // epilogue
#pragma unroll
    for (int mt = 0; mt < 4; mt++) {
        int r0 = rowBase + warpM * 64 + mt * 16 + gid;
#pragma unroll
        for (int nt = 0; nt < 2; nt++) {
            int c0 = colBase + warpN * 16 + nt * 8 + tig * 2;
            if (c0 < N)     C[(size_t)r0 * N + c0]           = acc[mt][nt][0];
            if (c0 + 1 < N) C[(size_t)r0 * N + c0 + 1]       = acc[mt][nt][1];
            if (c0 < N)     C[(size_t)(r0 + 8) * N + c0]     = acc[mt][nt][2];
            if (c0 + 1 < N) C[(size_t)(r0 + 8) * N + c0 + 1] = acc[mt][nt][3];
        }
    }
}

// ---------------- prep: round / transpose+round ----------------
__global__ __launch_bounds__(256) void round_kernel(const float* __restrict__ src,
                                                    float* __restrict__ dst, int n) {
    int i = blockIdx.x * 256 + threadIdx.x;
    if (i < n) dst[i] = f2tf32(src[i]);
}

__global__ void transpose_round_kernel(const float* __restrict__ src,
                                       float* __restrict__ dst, int R, int Cc) {
    __shared__ float t[32][33];
    int c0 = blockIdx.x * 32, r0 = blockIdx.y * 32;
    int x = c0 + threadIdx.x;
    for (int i = threadIdx.y; i < 32; i += 8) {
        int y = r0 + i;
        if (x < Cc && y < R) t[i][threadIdx.x] = src[(size_t)y * Cc + x];
    }
    __syncthreads();
    int xo = r0 + threadIdx.x;
    for (int i = threadIdx.y; i < 32; i += 8) {
        int yo = c0 + i;
        if (xo < R && yo < Cc) dst[(size_t)yo * R + xo] = f2tf32(t[threadIdx.x][i]);
    }
}

// ---------------- conv1d (causal depthwise, K=4) + bias + silu, float4 ----------------
__global__ __launch_bounds__(224) void conv_kernel(const float* __restrict__ cw,
                                                   const float* __restrict__ cb) {
    int c4 = blockIdx.x * 224 + threadIdx.x;   // 0..447
    int ch = c4 * 4;
    int t  = blockIdx.y;
    int b  = t / LSEQ, l = t % LSEQ;
    float4 acc = *reinterpret_cast<const float4*>(&cb[ch]);
#pragma unroll
    for (int k = 0; k < KC; k++) {
        int lp = l - (KC - 1) + k;
        if (lp >= 0) {
            float4 xv = *reinterpret_cast<const float4*>(&g_zx[(size_t)(b * LSEQ + lp) * NPROJ + IF + ch]);
            float4 wv = *reinterpret_cast<const float4*>(&cw[k * XBCW + ch]);
            acc.x = fmaf(xv.x, wv.x, acc.x);
            acc.y = fmaf(xv.y, wv.y, acc.y);
            acc.z = fmaf(xv.z, wv.z, acc.z);
            acc.w = fmaf(xv.w, wv.w, acc.w);
        }
    }
    acc.x = acc.x / (1.f + expf(-acc.x));
    acc.y = acc.y / (1.f + expf(-acc.y));
    acc.z = acc.z / (1.f + expf(-acc.z));
    acc.w = acc.w / (1.f + expf(-acc.w));
    *reinterpret_cast<float4*>(&g_xc[(size_t)t * XBCW + ch]) = acc;
}

// ---------------- dt: softplus(dt_raw + bias), clip>=0 ----------------
__global__ __launch_bounds__(256) void dt_kernel(const float* __restrict__ dtb) {
    int idx = blockIdx.x * 256 + threadIdx.x;
    if (idx >= TTOT * HH) return;
    int t = idx / HH, h = idx % HH;
    float x = g_zx[(size_t)t * NPROJ + (NPROJ - HH) + h] + dtb[h];
    float sp = (x > 0.f) ? (x + log1pf(expf(-x))) : log1pf(expf(x));
    g_dt[idx] = fmaxf(sp, 0.f);
}

// ---------------- per-chunk inclusive cumsum of A*dt ----------------
__global__ __launch_bounds__(256) void acum_kernel(const float* __restrict__ alog) {
    int bx = blockIdx.x;
    int c  = bx % CN;
    int h  = (bx / CN) % HH;
    int b  = bx / (CN * HH);
    int s  = threadIdx.x;
    int t  = b * LSEQ + c * CSZ + s;
    float A = -expf(alog[h]);
    __shared__ float a[CSZ];
    a[s] = A * g_dt[(size_t)t * HH + h];
    __syncthreads();
    for (int off = 1; off < CSZ; off <<= 1) {
        float add = (s >= off) ? a[s - off] : 0.f;
        __syncthreads();
        a[s] += add;
        __syncthreads();
    }
    g_ac[(size_t)((b * HH + h) * CN + c) * CSZ + s] = a[s];
}

// ================= chunk state via TF32 mma =================
#define CS_AS 68
#define CS_BS 136

__global__ __launch_bounds__(256) void chunkstate_mma_kernel() {
    extern __shared__ float sm[];
    float* As = sm;
    float* Bs = sm + 64 * CS_AS;

    int bx = blockIdx.x;
    int h = bx % HH;
    int c = (bx / HH) % CN;
    int b = bx / (HH * CN);
    int tid = threadIdx.x, lane = tid & 31, warpId = tid >> 5;
    int gid = lane >> 2, tig = lane & 3;
    int warpM = warpId & 1, warpN = warpId >> 1;
    int acbase = ((b * HH + h) * CN + c) * CSZ;
    int tbase = b * LSEQ + c * CSZ;
    float Asum = g_ac[acbase + CSZ - 1];

    float acc[2][4][4];
#pragma unroll
    for (int mt = 0; mt < 2; mt++)
#pragma unroll
        for (int nt = 0; nt < 4; nt++)
#pragma unroll
            for (int e = 0; e < 4; e++) acc[mt][nt][e] = 0.f;

    for (int kt = 0; kt < 4; kt++) {
        for (int i = tid; i < 64 * 64; i += 256) {
            int l = i >> 6, p = i & 63;
            int ts = tbase + kt * 64 + l;
            float v = g_xc[(size_t)ts * XBCW + h * PP + p] * g_dt[(size_t)ts * HH + h];
            As[p * CS_AS + l] = f2tf32(v);
        }
        for (int i = tid; i < 64 * 128; i += 256) {
            int l = i >> 7, n = i & 127;
            int ts = tbase + kt * 64 + l;
            float dec = expf(Asum - g_ac[acbase + kt * 64 + l]);
            Bs[l * CS_BS + n] = f2tf32(g_xc[(size_t)ts * XBCW + IF + n] * dec);
        }
        __syncthreads();
#pragma unroll
        for (int k8 = 0; k8 < 8; k8++) {
            int k0 = k8 * 8;
            uint32_t af[2][4];
#pragma unroll
            for (int mt = 0; mt < 2; mt++) {
                int m = warpM * 32 + mt * 16;
                af[mt][0] = fu(As[(m + gid) * CS_AS + k0 + tig]);
                af[mt][1] = fu(As[(m + gid + 8) * CS_AS + k0 + tig]);
                af[mt][2] = fu(As[(m + gid) * CS_AS + k0 + tig + 4]);
                af[mt][3] = fu(As[(m + gid + 8) * CS_AS + k0 + tig + 4]);
            }
#pragma unroll
            for (int nt = 0; nt < 4; nt++) {
                int n = warpN * 32 + nt * 8 + gid;
                uint32_t b0 = fu(Bs[(k0 + tig) * CS_BS + n]);
                uint32_t b1 = fu(Bs[(k0 + tig + 4) * CS_BS + n]);
#pragma unroll
                for (int mt = 0; mt < 2; mt++)
                    mma_tf32(acc[mt][nt], af[mt][0], af[mt][1], af[mt][2], af[mt][3], b0, b1);
            }
        }
        __syncthreads();
    }

    size_t base = ((size_t)((b * CN + c) * HH + h)) * PP * NST;
#pragma unroll
    for (int mt = 0; mt < 2; mt++) {
        int p0 = warpM * 32 + mt * 16 + gid;
#pragma unroll
        for (int nt = 0; nt < 4; nt++) {
            int n0 = warpN * 32 + nt * 8 + tig * 2;
            g_ls[base + (size_t)p0 * NST + n0]           = acc[mt][nt][0];
            g_ls[base + (size_t)p0 * NST + n0 + 1]       = acc[mt][nt][1];
            g_ls[base + (size_t)(p0 + 8) * NST + n0]     = acc[mt][nt][2];
            g_ls[base + (size_t)(p0 + 8) * NST + n0 + 1] = acc[mt][nt][3];
        }
    }
}

// ---------------- inter-chunk recurrence (1 element/thread) ----------------
__global__ __launch_bounds__(256) void recur_kernel() {
    int blk = blockIdx.x;            // BSZ*HH*32
    int seg = blk & 31;
    int bh  = blk >> 5;
    int b = bh / HH, h = bh % HH;
    int idx = seg * 256 + threadIdx.x;   // 0..8191
    float st = 0.f;
#pragma unroll
    for (int c = 0; c < CN; c++) {
        float es = expf(g_ac[(size_t)((b * HH + h) * CN + c) * CSZ + CSZ - 1]);
        size_t base = ((size_t)((b * CN + c) * HH + h)) * PP * NST;
        g_ps[base + idx] = st;
        st = fmaf(st, es, g_ls[base + idx]);
    }
}

// ================= Y via TF32 mma =================
#define YD_CS 132
#define YD_XS 72
#define YD_GS 68

__global__ __launch_bounds__(256) void ydiag_mma_kernel(const float* __restrict__ Darr) {
    extern __shared__ float sm[];
    float* Cs  = sm;
    float* Bst = Cs + 64 * YD_CS;
    float* Xs  = Bst + 64 * YD_CS;
    float* Gs  = Xs + 64 * YD_XS;
    float* aL  = Gs + 64 * YD_GS;
    float* aS  = aL + 64;

    int lt  = blockIdx.x;
    int bch = blockIdx.y;
    int h = bch % HH;
    int c = (bch / HH) % CN;
    int b = bch / (HH * CN);
    int tid = threadIdx.x, lane = tid & 31, warpId = tid >> 5;
    int gid = lane >> 2, tig = lane & 3;
    int m0 = (warpId & 3) * 16;
    int n0 = (warpId >> 2) * 32;
    int acbase = ((b * HH + h) * CN + c) * CSZ;
    int tbase = b * LSEQ + c * CSZ;

    for (int i = tid; i < 64 * 128; i += 256) {
        int l = i >> 7, n = i & 127;
        Cs[l * YD_CS + n] = f2tf32(g_xc[(size_t)(tbase + lt * 64 + l) * XBCW + IF + NST + n]);
    }
    if (tid < 64) aL[tid] = g_ac[acbase + lt * 64 + tid];

    float accD[4][4];
#pragma unroll
    for (int nt = 0; nt < 4; nt++)
#pragma unroll
        for (int e = 0; e < 4; e++) accD[nt][e] = 0.f;

    for (int st = 0; st <= lt; st++) {
        __syncthreads();
        for (int i = tid; i < 64 * 128; i += 256) {
            int s = i >> 7, n = i & 127;
            Bst[s * YD_CS + n] = f2tf32(g_xc[(size_t)(tbase + st * 64 + s) * XBCW + IF + n]);
        }
        for (int i = tid; i < 64 * 64; i += 256) {
            int s = i >> 6, p = i & 63;
            int ts = tbase + st * 64 + s;
            Xs[s * YD_XS + p] = f2tf32(g_xc[(size_t)ts * XBCW + h * PP + p] * g_dt[(size_t)ts * HH + h]);
        }
        if (tid < 64) aS[tid] = g_ac[acbase + st * 64 + tid];
        __syncthreads();

        float g4[4][4];
#pragma unroll
        for (int nt = 0; nt < 4; nt++)
#pragma unroll
            for (int e = 0; e < 4; e++) g4[nt][e] = 0.f;
#pragma unroll
        for (int k8 = 0; k8 < 16; k8++) {
            int k0 = k8 * 8;
            uint32_t a0 = fu(Cs[(m0 + gid) * YD_CS + k0 + tig]);
            uint32_t a1 = fu(Cs[(m0 + gid + 8) * YD_CS + k0 + tig]);
            uint32_t a2 = fu(Cs[(m0 + gid) * YD_CS + k0 + tig + 4]);
            uint32_t a3 = fu(Cs[(m0 + gid + 8) * YD_CS + k0 + tig + 4]);
#pragma unroll
            for (int nt = 0; nt < 4; nt++) {
                int s = n0 + nt * 8 + gid;
                uint32_t b0 = fu(Bst[s * YD_CS + k0 + tig]);
                uint32_t b1 = fu(Bst[s * YD_CS + k0 + tig + 4]);
                mma_tf32(g4[nt], a0, a1, a2, a3, b0, b1);
            }
        }
        {
            int lA = m0 + gid, lB = lA + 8;
            int glA = lt * 64 + lA, glB = glA + 8;
            float aLA = aL[lA], aLB = aL[lB];
#pragma unroll
            for (int nt = 0; nt < 4; nt++) {
                int s0 = n0 + nt * 8 + tig * 2;
                int gs0 = st * 64 + s0;
                float as0 = aS[s0], as1 = aS[s0 + 1];
                float v0 = (gs0     <= glA) ? g4[nt][0] * expf(aLA - as0) : 0.f;
                float v1 = (gs0 + 1 <= glA) ? g4[nt][1] * expf(aLA - as1) : 0.f;
                float v2 = (gs0     <= glB) ? g4[nt][2] * expf(aLB - as0) : 0.f;
                float v3 = (gs0 + 1 <= glB) ? g4[nt][3] * expf(aLB - as1) : 0.f;
                Gs[lA * YD_GS + s0]     = f2tf32(v0);
                Gs[lA * YD_GS + s0 + 1] = f2tf32(v1);
                Gs[lB * YD_GS + s0]     = f2tf32(v2);
                Gs[lB * YD_GS + s0 + 1] = f2tf32(v3);
            }
        }
        __syncthreads();
#pragma unroll
        for (int k8 = 0; k8 < 8; k8++) {
            int k0 = k8 * 8;
            uint32_t a0 = fu(Gs[(m0 + gid) * YD_GS + k0 + tig]);
            uint32_t a1 = fu(Gs[(m0 + gid + 8) * YD_GS + k0 + tig]);
            uint32_t a2 = fu(Gs[(m0 + gid) * YD_GS + k0 + tig + 4]);
            uint32_t a3 = fu(Gs[(m0 + gid + 8) * YD_GS + k0 + tig + 4]);
#pragma unroll
            for (int nt = 0; nt < 4; nt++) {
                int p = n0 + nt * 8 + gid;
                uint32_t b0 = fu(Xs[(k0 + tig) * YD_XS + p]);
                uint32_t b1 = fu(Xs[(k0 + tig + 4) * YD_XS + p]);
                mma_tf32(accD[nt], a0, a1, a2, a3, b0, b1);
            }
        }
    }

    __syncthreads();
    {
        size_t sbase = ((size_t)((b * CN + c) * HH + h)) * PP * NST;
        for (int i = tid; i < 64 * 128; i += 256) {
            int p = i >> 7, n = i & 127;
            Bst[p * YD_CS + n] = f2tf32(g_ps[sbase + (size_t)p * NST + n]);
        }
    }
    __syncthreads();
    float off4[4][4];
#pragma unroll
    for (int nt = 0; nt < 4; nt++)
#pragma unroll
        for (int e = 0; e < 4; e++) off4[nt][e] = 0.f;
#pragma unroll
    for (int k8 = 0; k8 < 16; k8++) {
        int k0 = k8 * 8;
        uint32_t a0 = fu(Cs[(m0 + gid) * YD_CS + k0 + tig]);
        uint32_t a1 = fu(Cs[(m0 + gid + 8) * YD_CS + k0 + tig]);
        uint32_t a2 = fu(Cs[(m0 + gid) * YD_CS + k0 + tig + 4]);
        uint32_t a3 = fu(Cs[(m0 + gid + 8) * YD_CS + k0 + tig + 4]);
#pragma unroll
        for (int nt = 0; nt < 4; nt++) {
            int p = n0 + nt * 8 + gid;
            uint32_t b0 = fu(Bst[p * YD_CS + k0 + tig]);
            uint32_t b1 = fu(Bst[p * YD_CS + k0 + tig + 4]);
            mma_tf32(off4[nt], a0, a1, a2, a3, b0, b1);
        }
    }

    {
        int lA = m0 + gid, lB = lA + 8;
        float e0 = expf(aL[lA]), e1 = expf(aL[lB]);
        float Dh = Darr[h];
        int tA = tbase + lt * 64 + lA;
        int tB = tbase + lt * 64 + lB;
#pragma unroll
        for (int nt = 0; nt < 4; nt++) {
            int p0 = n0 + nt * 8 + tig * 2;
            float xA0 = g_xc[(size_t)tA * XBCW + h * PP + p0];
            float xA1 = g_xc[(size_t)tA * XBCW + h * PP + p0 + 1];
            float xB0 = g_xc[(size_t)tB * XBCW + h * PP + p0];
            float xB1 = g_xc[(size_t)tB * XBCW + h * PP + p0 + 1];
            g_y[(size_t)tA * IF + h * PP + p0]     = accD[nt][0] + e0 * off4[nt][0] + Dh * xA0;
            g_y[(size_t)tA * IF + h * PP + p0 + 1] = accD[nt][1] + e0 * off4[nt][1] + Dh * xA1;
            g_y[(size_t)tB * IF + h * PP + p0]     = accD[nt][2] + e1 * off4[nt][2] + Dh * xB0;
            g_y[(size_t)tB * IF + h * PP + p0 + 1] = accD[nt][3] + e1 * off4[nt][3] + Dh * xB1;
        }
    }
}

// ---------------- gated RMSNorm (float4, stores tf32-rounded) ----------------
__global__ __launch_bounds__(128) void gnorm_kernel(const float* __restrict__ nw) {
    int t = blockIdx.x;
    int tid = threadIdx.x;
    float4 v[3];
    float ss = 0.f;
#pragma unroll
    for (int k = 0; k < 3; k++) {
        int i = (tid + k * 128) * 4;
        float4 y = *reinterpret_cast<const float4*>(&g_y[(size_t)t * IF + i]);
        float4 z = *reinterpret_cast<const float4*>(&g_zx[(size_t)t * NPROJ + i]);
        float x0 = y.x * (z.x / (1.f + expf(-z.x)));
        float x1 = y.y * (z.y / (1.f + expf(-z.y)));
        float x2 = y.z * (z.z / (1.f + expf(-z.z)));
        float x3 = y.w * (z.w / (1.f + expf(-z.w)));
        v[k] = make_float4(x0, x1, x2, x3);
        ss += x0 * x0 + x1 * x1 + x2 * x2 + x3 * x3;
    }
    __shared__ float red[128];
    __shared__ float s_scale;
    red[tid] = ss;
    __syncthreads();
    for (int o = 64; o > 0; o >>= 1) {
        if (tid < o) red[tid] += red[tid + o];
        __syncthreads();
    }
    if (tid == 0) s_scale = rsqrtf(red[0] / (float)IF + 1e-5f);
    __syncthreads();
    float sc = s_scale;
#pragma unroll
    for (int k = 0; k < 3; k++) {
        int i = (tid + k * 128) * 4;
        float4 w = *reinterpret_cast<const float4*>(&nw[i]);
        float4 o;
        o.x = f2tf32(v[k].x * sc * w.x);
        o.y = f2tf32(v[k].y * sc * w.y);
        o.z = f2tf32(v[k].z * sc * w.z);
        o.w = f2tf32(v[k].w * sc * w.w);
        *reinterpret_cast<float4*>(&g_y[(size_t)t * IF + i]) = o;
    }
}

// ---------------- host launcher ----------------
extern "C" void kernel_launch(void* const* d_in, const int* in_sizes, int n_in,
                              void* d_out, int out_size) {
    const float* hs   = (const float*)d_in[0];
    const float* inw  = (const float*)d_in[1];
    const float* cw   = (const float*)d_in[2];
    const float* cb   = (const float*)d_in[3];
    const float* dtb  = (const float*)d_in[4];
    const float* alog = (const float*)d_in[5];
    const float* Dp   = (const float*)d_in[6];
    const float* nw   = (const float*)d_in[7];
    const float* ow   = (const float*)d_in[8];
    float* out = (float*)d_out;

    void *p_zx = nullptr, *p_y = nullptr, *p_hsr = nullptr, *p_inwT = nullptr, *p_owT = nullptr;
    cudaGetSymbolAddress(&p_zx, g_zx);
    cudaGetSymbolAddress(&p_y, g_y);
    cudaGetSymbolAddress(&p_hsr, g_hsr);
    cudaGetSymbolAddress(&p_inwT, g_inwT);
    cudaGetSymbolAddress(&p_owT, g_owT);

    int smem_gemm = NSTAGE * STAGE_F * 4;   // 61440
    int smem_cs = (64 * CS_AS + 64 * CS_BS) * 4;
    int smem_y  = (64 * YD_CS * 2 + 64 * YD_XS + 64 * YD_GS + 128) * 4;
    cudaFuncSetAttribute(tf32gemm_ldsm_kernel, cudaFuncAttributeMaxDynamicSharedMemorySize, smem_gemm);
    cudaFuncSetAttribute(chunkstate_mma_kernel, cudaFuncAttributeMaxDynamicSharedMemorySize, smem_cs);
    cudaFuncSetAttribute(ydiag_mma_kernel, cudaFuncAttributeMaxDynamicSharedMemorySize, smem_y);

    // 0. prep: round hs; transpose+round weights
    round_kernel<<<(TTOT * HIDD + 255) / 256, 256>>>(hs, (float*)p_hsr, TTOT * HIDD);
    {
        dim3 g((NPROJ + 31) / 32, (HIDD + 31) / 32);
        transpose_round_kernel<<<g, dim3(32, 8)>>>(inw, (float*)p_inwT, HIDD, NPROJ);
    }
    {
        dim3 g((HIDD + 31) / 32, (IF + 31) / 32);
        transpose_round_kernel<<<g, dim3(32, 8)>>>(ow, (float*)p_owT, IF, HIDD);
    }

    // 1. in_proj GEMM: (8192 x 768) @ (768 x 3352)
    {
        dim3 grid((NPROJ + 63) / 64, TTOT / 128);
        tf32gemm_ldsm_kernel<<<grid, 256, smem_gemm>>>((const float*)p_hsr, (const float*)p_inwT,
                                                       (float*)p_zx, TTOT, NPROJ, HIDD);
    }
    // 2. conv + silu (float4)
    {
        dim3 grid(2, TTOT);
        conv_kernel<<<grid, 224>>>(cw, cb);
    }
    // 3. dt softplus
    dt_kernel<<<(TTOT * HH + 255) / 256, 256>>>(dtb);
    // 4. per-chunk cumsum of A*dt
    acum_kernel<<<BSZ * HH * CN, 256>>>(alog);
    // 5. local chunk states (tf32 mma)
    chunkstate_mma_kernel<<<BSZ * CN * HH, 256, smem_cs>>>();
    // 6. inter-chunk recurrence (wide)
    recur_kernel<<<BSZ * HH * 32, 256>>>();
    // 7. Y_diag + Y_off + D residual (tf32 mma)
    {
        dim3 grid(4, BSZ * CN * HH);
        ydiag_mma_kernel<<<grid, 256, smem_y>>>(Dp);
    }
    // 8. gated RMSNorm (writes tf32-rounded)
    gnorm_kernel<<<TTOT, 128>>>(nw);
    // 9. out_proj GEMM: (8192 x 1536) @ (1536 x 768) -> d_out
    {
        dim3 grid((HIDD + 63) / 64, TTOT / 128);
        tf32gemm_ldsm_kernel<<<grid, 256, smem_gemm>>>((const float*)p_y, (const float*)p_owT,
                                                       out, TTOT, HIDD, IF);
    }
}

// round 8
// speedup vs baseline: 1.0811x; 1.0811x over previous
#include <cuda_runtime.h>
#include <cuda_bf16.h>
#include <math.h>
#include <stdint.h>

// ---------------- problem constants ----------------
#define BSZ   2
#define LSEQ  4096
#define TTOT  8192          // BSZ*LSEQ
#define HIDD  768
#define IF    1536          // I
#define NST   128           // N
#define HH    24            // H
#define PP    64            // P
#define CSZ   256           // chunk size
#define CN    16            // LSEQ/CSZ
#define KC    4             // conv kernel
#define NPROJ 3352          // 2*(I+N)+H
#define XBCW  1792          // I+2N

// ---------------- scratch (static device globals; no allocs) ----------------
__device__ float g_zx[TTOT * NPROJ];               // in_proj output (z | xBC | dt)
__device__ float g_xc[TTOT * XBCW];                // conv+silu output
__device__ float g_dt[TTOT * HH];                  // softplus(dt+bias)
__device__ float g_ac[BSZ * HH * CN * CSZ];        // per-chunk inclusive cumsum of A*dt
__device__ float g_ls[BSZ * CN * HH * PP * NST];   // local chunk states
__device__ float g_ps[BSZ * CN * HH * PP * NST];   // prefix states entering chunk
__device__ float g_y [TTOT * IF];                  // y (tf32-rounded after gnorm)
__device__ float g_hsr [TTOT * HIDD];              // hs rounded to tf32
__device__ float g_inwT[NPROJ * HIDD];             // in_proj_w^T, tf32
__device__ float g_owT [HIDD * IF];                // out_proj_w^T, tf32

// ---------------- helpers ----------------
__device__ __forceinline__ float f2tf32(float x) {
    uint32_t r;
    asm("cvt.rna.tf32.f32 %0, %1;" : "=r"(r) : "f"(x));
    return __uint_as_float(r);
}
__device__ __forceinline__ uint32_t fu(float x) { return __float_as_uint(x); }

__device__ __forceinline__ void mma_tf32(float* c, uint32_t a0, uint32_t a1,
                                         uint32_t a2, uint32_t a3,
                                         uint32_t b0, uint32_t b1) {
    asm volatile(
        "mma.sync.aligned.m16n8k8.row.col.f32.tf32.tf32.f32 "
        "{%0,%1,%2,%3}, {%4,%5,%6,%7}, {%8,%9}, {%0,%1,%2,%3};\n"
        : "+f"(c[0]), "+f"(c[1]), "+f"(c[2]), "+f"(c[3])
        : "r"(a0), "r"(a1), "r"(a2), "r"(a3), "r"(b0), "r"(b1));
}
__device__ __forceinline__ void ldsm_x4(uint32_t addr, uint32_t& r0, uint32_t& r1,
                                        uint32_t& r2, uint32_t& r3) {
    asm volatile("ldmatrix.sync.aligned.m8n8.x4.shared.b16 {%0,%1,%2,%3}, [%4];"
                 : "=r"(r0), "=r"(r1), "=r"(r2), "=r"(r3) : "r"(addr));
}
__device__ __forceinline__ void cpasync16(uint32_t daddr, const void* gaddr, bool pred) {
    int sz = pred ? 16 : 0;
    asm volatile("cp.async.cg.shared.global [%0], [%1], 16, %2;"
                 :: "r"(daddr), "l"(gaddr), "r"(sz));
}
#define CP_COMMIT()  asm volatile("cp.async.commit_group;")
#define CP_WAIT3()   asm volatile("cp.async.wait_group 3;")

// ================= TF32 GEMM (round-6 best config): BK=16, 5 stages, BN=128 =================
#define GST 20               // row stride (floats): 16 + 4 pad
#define STAGE_F (128 * GST)  // floats per matrix per stage
#define NSTAGE 5

__global__ __launch_bounds__(256, 2) void tf32gemm_ldsm_kernel(const float* __restrict__ A,
                                                               const float* __restrict__ Bt,
                                                               float* __restrict__ C,
                                                               int M, int N, int K) {
    extern __shared__ float sm[];
    const int tid = threadIdx.x;
    const int lane = tid & 31;
    const int warpId = tid >> 5;
    const int gid = lane >> 2, tig = lane & 3;
    const int warpM = warpId & 1;
    const int warpN = warpId >> 1;
    const int rowBase = blockIdx.y * 128;
    const int colBase = blockIdx.x * 128;
    const int nk = K >> 4;

    uint32_t smBase = (uint32_t)__cvta_generic_to_shared(sm);

    const int cpr = tid >> 1;
    const int cpc = (tid & 1) * 2;
    const int nB = colBase + cpr;
    const bool bOK = nB < N;
    const int nBc = bOK ? nB : 0;
    const uint32_t cpOff = (uint32_t)(cpr * GST + cpc * 4) * 4;

    auto issue = [&](int kt, int stage) {
        int k0 = kt << 4;
        uint32_t sA = smBase + (uint32_t)(stage * 2 * STAGE_F) * 4 + cpOff;
        uint32_t sB = smBase + (uint32_t)((stage * 2 + 1) * STAGE_F) * 4 + cpOff;
        const float* ga = &A[(size_t)(rowBase + cpr) * K + k0 + cpc * 4];
        const float* gb = &Bt[(size_t)nBc * K + k0 + cpc * 4];
        cpasync16(sA, ga, true);
        cpasync16(sA + 16, ga + 4, true);
        cpasync16(sB, gb, bOK);
        cpasync16(sB + 16, gb + 4, bOK);
        CP_COMMIT();
    };

    const uint32_t aLaneOff = (uint32_t)((lane & 15) * GST + (lane >> 4) * 4);
    const uint32_t bLaneOff = (uint32_t)(((lane >> 4) * 8 + (lane & 7)) * GST + ((lane >> 3) & 1) * 4);

    float acc[4][4][4];
#pragma unroll
    for (int mt = 0; mt < 4; mt++)
#pragma unroll
        for (int nt = 0; nt < 4; nt++)
#pragma unroll
            for (int e = 0; e < 4; e++) acc[mt][nt][e] = 0.f;

#pragma unroll
    for (int p = 0; p < NSTAGE - 1; p++)
        if (p < nk) issue(p, p);

    for (int kt = 0; kt < nk; kt++) {
        CP_WAIT3();
        __syncthreads();
        if (kt + NSTAGE - 1 < nk) issue(kt + NSTAGE - 1, (kt + NSTAGE - 1) % NSTAGE);

        int stage = kt % NSTAGE;
        uint32_t aBase = smBase + (uint32_t)(stage * 2 * STAGE_F) * 4;
        uint32_t bBase = smBase + (uint32_t)((stage * 2 + 1) * STAGE_F) * 4;

#pragma unroll
        for (int ks = 0; ks < 2; ks++) {
            uint32_t bfr[4][2];
#pragma unroll
            for (int pair = 0; pair < 2; pair++) {
                uint32_t addr = bBase + ((uint32_t)((warpN * 32 + pair * 16) * GST + ks * 8) + bLaneOff) * 4;
                uint32_t r0, r1, r2, r3;
                ldsm_x4(addr, r0, r1, r2, r3);
                bfr[pair * 2][0] = r0; bfr[pair * 2][1] = r1;
                bfr[pair * 2 + 1][0] = r2; bfr[pair * 2 + 1][1] = r3;
            }
#pragma unroll
            for (int mt = 0; mt < 4; mt++) {
                uint32_t addr = aBase + ((uint32_t)((warpM * 64 + mt * 16) * GST + ks * 8) + aLaneOff) * 4;
                uint32_t a0, a1, a2, a3;
                ldsm_x4(addr, a0, a1, a2, a3);
#pragma unroll
                for (int nt = 0; nt < 4; nt++)
                    mma_tf32(acc[mt][nt], a0, a1, a2, a3, bfr[nt][0], bfr[nt][1]);
            }
        }
    }

#pragma unroll
    for (int mt = 0; mt < 4; mt++) {
        int r0 = rowBase + warpM * 64 + mt * 16 + gid;
#pragma unroll
        for (int nt = 0; nt < 4; nt++) {
            int c0 = colBase + warpN * 32 + nt * 8 + tig * 2;
            if (c0 < N)     C[(size_t)r0 * N + c0]           = acc[mt][nt][0];
            if (c0 + 1 < N) C[(size_t)r0 * N + c0 + 1]       = acc[mt][nt][1];
            if (c0 < N)     C[(size_t)(r0 + 8) * N + c0]     = acc[mt][nt][2];
            if (c0 + 1 < N) C[(size_t)(r0 + 8) * N + c0 + 1] = acc[mt][nt][3];
        }
    }
}

// ---------------- prep: round / transpose+round ----------------
__global__ __launch_bounds__(256) void round_kernel(const float* __restrict__ src,
                                                    float* __restrict__ dst, int n) {
    int i = blockIdx.x * 256 + threadIdx.x;
    if (i < n) dst[i] = f2tf32(src[i]);
}

__global__ void transpose_round_kernel(const float* __restrict__ src,
                                       float* __restrict__ dst, int R, int Cc) {
    __shared__ float t[32][33];
    int c0 = blockIdx.x * 32, r0 = blockIdx.y * 32;
    int x = c0 + threadIdx.x;
    for (int i = threadIdx.y; i < 32; i += 8) {
        int y = r0 + i;
        if (x < Cc && y < R) t[i][threadIdx.x] = src[(size_t)y * Cc + x];
    }
    __syncthreads();
    int xo = r0 + threadIdx.x;
    for (int i = threadIdx.y; i < 32; i += 8) {
        int yo = c0 + i;
        if (xo < R && yo < Cc) dst[(size_t)yo * R + xo] = f2tf32(t[threadIdx.x][i]);
    }
}

// ---------------- conv1d (causal depthwise, K=4) + bias + silu, float4 ----------------
__global__ __launch_bounds__(224) void conv_kernel(const float* __restrict__ cw,
                                                   const float* __restrict__ cb) {
    int c4 = blockIdx.x * 224 + threadIdx.x;   // 0..447
    int ch = c4 * 4;
    int t  = blockIdx.y;
    int b  = t / LSEQ, l = t % LSEQ;
    float4 acc = *reinterpret_cast<const float4*>(&cb[ch]);
#pragma unroll
    for (int k = 0; k < KC; k++) {
        int lp = l - (KC - 1) + k;
        if (lp >= 0) {
            float4 xv = *reinterpret_cast<const float4*>(&g_zx[(size_t)(b * LSEQ + lp) * NPROJ + IF + ch]);
            float4 wv = *reinterpret_cast<const float4*>(&cw[k * XBCW + ch]);
            acc.x = fmaf(xv.x, wv.x, acc.x);
            acc.y = fmaf(xv.y, wv.y, acc.y);
            acc.z = fmaf(xv.z, wv.z, acc.z);
            acc.w = fmaf(xv.w, wv.w, acc.w);
        }
    }
    acc.x = acc.x / (1.f + expf(-acc.x));
    acc.y = acc.y / (1.f + expf(-acc.y));
    acc.z = acc.z / (1.f + expf(-acc.z));
    acc.w = acc.w / (1.f + expf(-acc.w));
    *reinterpret_cast<float4*>(&g_xc[(size_t)t * XBCW + ch]) = acc;
}

// ---------------- dt: softplus(dt_raw + bias), clip>=0 ----------------
__global__ __launch_bounds__(256) void dt_kernel(const float* __restrict__ dtb) {
    int idx = blockIdx.x * 256 + threadIdx.x;
    if (idx >= TTOT * HH) return;
    int t = idx / HH, h = idx % HH;
    float x = g_zx[(size_t)t * NPROJ + (NPROJ - HH) + h] + dtb[h];
    float sp = (x > 0.f) ? (x + log1pf(expf(-x))) : log1pf(expf(x));
    g_dt[idx] = fmaxf(sp, 0.f);
}

// ---------------- per-chunk inclusive cumsum of A*dt ----------------
__global__ __launch_bounds__(256) void acum_kernel(const float* __restrict__ alog) {
    int bx = blockIdx.x;
    int c  = bx % CN;
    int h  = (bx / CN) % HH;
    int b  = bx / (CN * HH);
    int s  = threadIdx.x;
    int t  = b * LSEQ + c * CSZ + s;
    float A = -expf(alog[h]);
    __shared__ float a[CSZ];
    a[s] = A * g_dt[(size_t)t * HH + h];
    __syncthreads();
    for (int off = 1; off < CSZ; off <<= 1) {
        float add = (s >= off) ? a[s - off] : 0.f;
        __syncthreads();
        a[s] += add;
        __syncthreads();
    }
    g_ac[(size_t)((b * HH + h) * CN + c) * CSZ + s] = a[s];
}

// ================= chunk state via TF32 mma + ldmatrix =================
// As: Xd^T [p][l] stride 68 (A-operand). Bs: decB^T [n][l] stride 68 (B-operand [n][k]).
#define CS_ST 68

__global__ __launch_bounds__(256) void chunkstate_mma_kernel() {
    extern __shared__ float sm[];
    float* As = sm;                    // 64 x 68
    float* Bs = sm + 64 * CS_ST;       // 128 x 68

    int bx = blockIdx.x;
    int h = bx % HH;
    int c = (bx / HH) % CN;
    int b = bx / (HH * CN);
    int tid = threadIdx.x, lane = tid & 31, warpId = tid >> 5;
    int gid = lane >> 2, tig = lane & 3;
    int warpM = warpId & 1, warpN = warpId >> 1;
    int acbase = ((b * HH + h) * CN + c) * CSZ;
    int tbase = b * LSEQ + c * CSZ;
    float Asum = g_ac[acbase + CSZ - 1];

    uint32_t smB = (uint32_t)__cvta_generic_to_shared(sm);
    uint32_t asB = smB;
    uint32_t bsB = smB + (uint32_t)(64 * CS_ST) * 4;
    const uint32_t aOff = (uint32_t)((lane & 15) * CS_ST + (lane >> 4) * 4);
    const uint32_t bOff = (uint32_t)(((lane >> 4) * 8 + (lane & 7)) * CS_ST + ((lane >> 3) & 1) * 4);

    float acc[2][4][4];
#pragma unroll
    for (int mt = 0; mt < 2; mt++)
#pragma unroll
        for (int nt = 0; nt < 4; nt++)
#pragma unroll
            for (int e = 0; e < 4; e++) acc[mt][nt][e] = 0.f;

    for (int kt = 0; kt < 4; kt++) {
        for (int i = tid; i < 64 * 64; i += 256) {
            int l = i >> 6, p = i & 63;
            int ts = tbase + kt * 64 + l;
            float v = g_xc[(size_t)ts * XBCW + h * PP + p] * g_dt[(size_t)ts * HH + h];
            As[p * CS_ST + l] = f2tf32(v);
        }
        for (int i = tid; i < 64 * 128; i += 256) {
            int l = i >> 7, n = i & 127;
            int ts = tbase + kt * 64 + l;
            float dec = expf(Asum - g_ac[acbase + kt * 64 + l]);
            Bs[n * CS_ST + l] = f2tf32(g_xc[(size_t)ts * XBCW + IF + n] * dec);
        }
        __syncthreads();
#pragma unroll
        for (int k8 = 0; k8 < 8; k8++) {
            int k0 = k8 * 8;
            uint32_t af[2][4];
#pragma unroll
            for (int mt = 0; mt < 2; mt++)
                ldsm_x4(asB + (uint32_t)((warpM * 32 + mt * 16) * CS_ST + k0 + aOff) * 4,
                        af[mt][0], af[mt][1], af[mt][2], af[mt][3]);
#pragma unroll
            for (int p2 = 0; p2 < 2; p2++) {
                uint32_t b0, b1, b2, b3;
                ldsm_x4(bsB + (uint32_t)((warpN * 32 + p2 * 16) * CS_ST + k0 + bOff) * 4, b0, b1, b2, b3);
#pragma unroll
                for (int mt = 0; mt < 2; mt++) {
                    mma_tf32(acc[mt][p2 * 2],     af[mt][0], af[mt][1], af[mt][2], af[mt][3], b0, b1);
                    mma_tf32(acc[mt][p2 * 2 + 1], af[mt][0], af[mt][1], af[mt][2], af[mt][3], b2, b3);
                }
            }
        }
        __syncthreads();
    }

    size_t base = ((size_t)((b * CN + c) * HH + h)) * PP * NST;
#pragma unroll
    for (int mt = 0; mt < 2; mt++) {
        int p0 = warpM * 32 + mt * 16 + gid;
#pragma unroll
        for (int nt = 0; nt < 4; nt++) {
            int n0 = warpN * 32 + nt * 8 + tig * 2;
            g_ls[base + (size_t)p0 * NST + n0]           = acc[mt][nt][0];
            g_ls[base + (size_t)p0 * NST + n0 + 1]       = acc[mt][nt][1];
            g_ls[base + (size_t)(p0 + 8) * NST + n0]     = acc[mt][nt][2];
            g_ls[base + (size_t)(p0 + 8) * NST + n0 + 1] = acc[mt][nt][3];
        }
    }
}

// ---------------- inter-chunk recurrence (1 element/thread) ----------------
__global__ __launch_bounds__(256) void recur_kernel() {
    int blk = blockIdx.x;            // BSZ*HH*32
    int seg = blk & 31;
    int bh  = blk >> 5;
    int b = bh / HH, h = bh % HH;
    int idx = seg * 256 + threadIdx.x;   // 0..8191
    float st = 0.f;
#pragma unroll
    for (int c = 0; c < CN; c++) {
        float es = expf(g_ac[(size_t)((b * HH + h) * CN + c) * CSZ + CSZ - 1]);
        size_t base = ((size_t)((b * CN + c) * HH + h)) * PP * NST;
        g_ps[base + idx] = st;
        st = fmaf(st, es, g_ls[base + idx]);
    }
}

// ================= Y via TF32 mma + ldmatrix =================
// Cs [l][n] 132; Bst [s|p][n] 132 (B-operand [n][k]); Xs transposed [p][s] 68;
// Gs [l][s] 68 (A-operand).
#define YD_CS 132
#define YD_XS 68
#define YD_GS 68

__global__ __launch_bounds__(256) void ydiag_mma_kernel(const float* __restrict__ Darr) {
    extern __shared__ float sm[];
    float* Cs  = sm;                        // 64 x 132
    float* Bst = Cs + 64 * YD_CS;           // 64 x 132
    float* Xs  = Bst + 64 * YD_CS;          // 64 x 68 (transposed [p][s])
    float* Gs  = Xs + 64 * YD_XS;           // 64 x 68
    float* aL  = Gs + 64 * YD_GS;
    float* aS  = aL + 64;

    int lt  = blockIdx.x;
    int bch = blockIdx.y;
    int h = bch % HH;
    int c = (bch / HH) % CN;
    int b = bch / (HH * CN);
    int tid = threadIdx.x, lane = tid & 31, warpId = tid >> 5;
    int gid = lane >> 2, tig = lane & 3;
    int m0 = (warpId & 3) * 16;
    int n0 = (warpId >> 2) * 32;
    int acbase = ((b * HH + h) * CN + c) * CSZ;
    int tbase = b * LSEQ + c * CSZ;

    uint32_t smB = (uint32_t)__cvta_generic_to_shared(sm);
    uint32_t csB  = smB;
    uint32_t bstB = smB + (uint32_t)(64 * YD_CS) * 4;
    uint32_t xsB  = bstB + (uint32_t)(64 * YD_CS) * 4;
    uint32_t gsB  = xsB + (uint32_t)(64 * YD_XS) * 4;

    const uint32_t aOff132 = (uint32_t)((lane & 15) * YD_CS + (lane >> 4) * 4);
    const uint32_t aOff68  = (uint32_t)((lane & 15) * YD_GS + (lane >> 4) * 4);
    const uint32_t bOff132 = (uint32_t)(((lane >> 4) * 8 + (lane & 7)) * YD_CS + ((lane >> 3) & 1) * 4);
    const uint32_t bOff68  = (uint32_t)(((lane >> 4) * 8 + (lane & 7)) * YD_XS + ((lane >> 3) & 1) * 4);

    for (int i = tid; i < 64 * 128; i += 256) {
        int l = i >> 7, n = i & 127;
        Cs[l * YD_CS + n] = f2tf32(g_xc[(size_t)(tbase + lt * 64 + l) * XBCW + IF + NST + n]);
    }
    if (tid < 64) aL[tid] = g_ac[acbase + lt * 64 + tid];

    float accD[4][4];
#pragma unroll
    for (int nt = 0; nt < 4; nt++)
#pragma unroll
        for (int e = 0; e < 4; e++) accD[nt][e] = 0.f;

    for (int st = 0; st <= lt; st++) {
        __syncthreads();
        for (int i = tid; i < 64 * 128; i += 256) {
            int s = i >> 7, n = i & 127;
            Bst[s * YD_CS + n] = f2tf32(g_xc[(size_t)(tbase + st * 64 + s) * XBCW + IF + n]);
        }
        for (int i = tid; i < 64 * 64; i += 256) {
            int s = i >> 6, p = i & 63;
            int ts = tbase + st * 64 + s;
            Xs[p * YD_XS + s] = f2tf32(g_xc[(size_t)ts * XBCW + h * PP + p] * g_dt[(size_t)ts * HH + h]);
        }
        if (tid < 64) aS[tid] = g_ac[acbase + st * 64 + tid];
        __syncthreads();

        // ---- G = C @ B^T (K = 128) ----
        float g4[4][4];
#pragma unroll
        for (int nt = 0; nt < 4; nt++)
#pragma unroll
            for (int e = 0; e < 4; e++) g4[nt][e] = 0.f;
#pragma unroll
        for (int k8 = 0; k8 < 16; k8++) {
            int k0 = k8 * 8;
            uint32_t a0, a1, a2, a3;
            ldsm_x4(csB + (uint32_t)(m0 * YD_CS + k0 + aOff132) * 4, a0, a1, a2, a3);
#pragma unroll
            for (int p2 = 0; p2 < 2; p2++) {
                uint32_t b0, b1, b2, b3;
                ldsm_x4(bstB + (uint32_t)((n0 + p2 * 16) * YD_CS + k0 + bOff132) * 4, b0, b1, b2, b3);
                mma_tf32(g4[p2 * 2],     a0, a1, a2, a3, b0, b1);
                mma_tf32(g4[p2 * 2 + 1], a0, a1, a2, a3, b2, b3);
            }
        }
        // ---- mask + decay in registers, spill to Gs ----
        {
            int lA = m0 + gid, lB = lA + 8;
            int glA = lt * 64 + lA, glB = glA + 8;
            float aLA = aL[lA], aLB = aL[lB];
#pragma unroll
            for (int nt = 0; nt < 4; nt++) {
                int s0 = n0 + nt * 8 + tig * 2;
                int gs0 = st * 64 + s0;
                float as0 = aS[s0], as1 = aS[s0 + 1];
                float v0 = (gs0     <= glA) ? g4[nt][0] * expf(aLA - as0) : 0.f;
                float v1 = (gs0 + 1 <= glA) ? g4[nt][1] * expf(aLA - as1) : 0.f;
                float v2 = (gs0     <= glB) ? g4[nt][2] * expf(aLB - as0) : 0.f;
                float v3 = (gs0 + 1 <= glB) ? g4[nt][3] * expf(aLB - as1) : 0.f;
                Gs[lA * YD_GS + s0]     = f2tf32(v0);
                Gs[lA * YD_GS + s0 + 1] = f2tf32(v1);
                Gs[lB * YD_GS + s0]     = f2tf32(v2);
                Gs[lB * YD_GS + s0 + 1] = f2tf32(v3);
            }
        }
        __syncthreads();
        // ---- acc += G @ Xd (K = 64), Xs is [p][s] ----
#pragma unroll
        for (int k8 = 0; k8 < 8; k8++) {
            int k0 = k8 * 8;
            uint32_t a0, a1, a2, a3;
            ldsm_x4(gsB + (uint32_t)(m0 * YD_GS + k0 + aOff68) * 4, a0, a1, a2, a3);
#pragma unroll
            for (int p2 = 0; p2 < 2; p2++) {
                uint32_t b0, b1, b2, b3;
                ldsm_x4(xsB + (uint32_t)((n0 + p2 * 16) * YD_XS + k0 + bOff68) * 4, b0, b1, b2, b3);
                mma_tf32(accD[p2 * 2],     a0, a1, a2, a3, b0, b1);
                mma_tf32(accD[p2 * 2 + 1], a0, a1, a2, a3, b2, b3);
            }
        }
    }

    // ---- off part: off = C @ S^T (K = 128) ----
    __syncthreads();
    {
        size_t sbase = ((size_t)((b * CN + c) * HH + h)) * PP * NST;
        for (int i = tid; i < 64 * 128; i += 256) {
            int p = i >> 7, n = i & 127;
            Bst[p * YD_CS + n] = f2tf32(g_ps[sbase + (size_t)p * NST + n]);
        }
    }
    __syncthreads();
    float off4[4][4];
#pragma unroll
    for (int nt = 0; nt < 4; nt++)
#pragma unroll
        for (int e = 0; e < 4; e++) off4[nt][e] = 0.f;
#pragma unroll
    for (int k8 = 0; k8 < 16; k8++) {
        int k0 = k8 * 8;
        uint32_t a0, a1, a2, a3;
        ldsm_x4(csB + (uint32_t)(m0 * YD_CS + k0 + aOff132) * 4, a0, a1, a2, a3);
#pragma unroll
        for (int p2 = 0; p2 < 2; p2++) {
            uint32_t b0, b1, b2, b3;
            ldsm_x4(bstB + (uint32_t)((n0 + p2 * 16) * YD_CS + k0 + bOff132) * 4, b0, b1, b2, b3);
            mma_tf32(off4[p2 * 2],     a0, a1, a2, a3, b0, b1);
            mma_tf32(off4[p2 * 2 + 1], a0, a1, a2, a3, b2, b3);
        }
    }

    // ---- epilogue: y = accD + exp(aL)*off + D*x ----
    {
        int lA = m0 + gid, lB = lA + 8;
        float e0 = expf(aL[lA]), e1 = expf(aL[lB]);
        float Dh = Darr[h];
        int tA = tbase + lt * 64 + lA;
        int tB = tbase + lt * 64 + lB;
#pragma unroll
        for (int nt = 0; nt < 4; nt++) {
            int p0 = n0 + nt * 8 + tig * 2;
            float xA0 = g_xc[(size_t)tA * XBCW + h * PP + p0];
            float xA1 = g_xc[(size_t)tA * XBCW + h * PP + p0 + 1];
            float xB0 = g_xc[(size_t)tB * XBCW + h * PP + p0];
            float xB1 = g_xc[(size_t)tB * XBCW + h * PP + p0 + 1];
            g_y[(size_t)tA * IF + h * PP + p0]     = accD[nt][0] + e0 * off4[nt][0] + Dh * xA0;
            g_y[(size_t)tA * IF + h * PP + p0 + 1] = accD[nt][1] + e0 * off4[nt][1] + Dh * xA1;
            g_y[(size_t)tB * IF + h * PP + p0]     = accD[nt][2] + e1 * off4[nt][2] + Dh * xB0;
            g_y[(size_t)tB * IF + h * PP + p0 + 1] = accD[nt][3] + e1 * off4[nt][3] + Dh * xB1;
        }
    }
}

// ---------------- gated RMSNorm (float4, stores tf32-rounded) ----------------
__global__ __launch_bounds__(128) void gnorm_kernel(const float* __restrict__ nw) {
    int t = blockIdx.x;
    int tid = threadIdx.x;
    float4 v[3];
    float ss = 0.f;
#pragma unroll
    for (int k = 0; k < 3; k++) {
        int i = (tid + k * 128) * 4;
        float4 y = *reinterpret_cast<const float4*>(&g_y[(size_t)t * IF + i]);
        float4 z = *reinterpret_cast<const float4*>(&g_zx[(size_t)t * NPROJ + i]);
        float x0 = y.x * (z.x / (1.f + expf(-z.x)));
        float x1 = y.y * (z.y / (1.f + expf(-z.y)));
        float x2 = y.z * (z.z / (1.f + expf(-z.z)));
        float x3 = y.w * (z.w / (1.f + expf(-z.w)));
        v[k] = make_float4(x0, x1, x2, x3);
        ss += x0 * x0 + x1 * x1 + x2 * x2 + x3 * x3;
    }
    __shared__ float red[128];
    __shared__ float s_scale;
    red[tid] = ss;
    __syncthreads();
    for (int o = 64; o > 0; o >>= 1) {
        if (tid < o) red[tid] += red[tid + o];
        __syncthreads();
    }
    if (tid == 0) s_scale = rsqrtf(red[0] / (float)IF + 1e-5f);
    __syncthreads();
    float sc = s_scale;
#pragma unroll
    for (int k = 0; k < 3; k++) {
        int i = (tid + k * 128) * 4;
        float4 w = *reinterpret_cast<const float4*>(&nw[i]);
        float4 o;
        o.x = f2tf32(v[k].x * sc * w.x);
        o.y = f2tf32(v[k].y * sc * w.y);
        o.z = f2tf32(v[k].z * sc * w.z);
        o.w = f2tf32(v[k].w * sc * w.w);
        *reinterpret_cast<float4*>(&g_y[(size_t)t * IF + i]) = o;
    }
}

// ---------------- host launcher ----------------
extern "C" void kernel_launch(void* const* d_in, const int* in_sizes, int n_in,
                              void* d_out, int out_size) {
    const float* hs   = (const float*)d_in[0];
    const float* inw  = (const float*)d_in[1];
    const float* cw   = (const float*)d_in[2];
    const float* cb   = (const float*)d_in[3];
    const float* dtb  = (const float*)d_in[4];
    const float* alog = (const float*)d_in[5];
    const float* Dp   = (const float*)d_in[6];
    const float* nw   = (const float*)d_in[7];
    const float* ow   = (const float*)d_in[8];
    float* out = (float*)d_out;

    void *p_zx = nullptr, *p_y = nullptr, *p_hsr = nullptr, *p_inwT = nullptr, *p_owT = nullptr;
    cudaGetSymbolAddress(&p_zx, g_zx);
    cudaGetSymbolAddress(&p_y, g_y);
    cudaGetSymbolAddress(&p_hsr, g_hsr);
    cudaGetSymbolAddress(&p_inwT, g_inwT);
    cudaGetSymbolAddress(&p_owT, g_owT);

    int smem_gemm = NSTAGE * 2 * STAGE_F * 4;                               // 102400
    int smem_cs = (64 * CS_ST + 128 * CS_ST) * 4;                            // 52224
    int smem_y  = (64 * YD_CS * 2 + 64 * YD_XS + 64 * YD_GS + 128) * 4;      // ~103.4KB
    cudaFuncSetAttribute(tf32gemm_ldsm_kernel, cudaFuncAttributeMaxDynamicSharedMemorySize, smem_gemm);
    cudaFuncSetAttribute(chunkstate_mma_kernel, cudaFuncAttributeMaxDynamicSharedMemorySize, smem_cs);
    cudaFuncSetAttribute(ydiag_mma_kernel, cudaFuncAttributeMaxDynamicSharedMemorySize, smem_y);

    // 0. prep: round hs; transpose+round weights
    round_kernel<<<(TTOT * HIDD + 255) / 256, 256>>>(hs, (float*)p_hsr, TTOT * HIDD);
    {
        dim3 g((NPROJ + 31) / 32, (HIDD + 31) / 32);
        transpose_round_kernel<<<g, dim3(32, 8)>>>(inw, (float*)p_inwT, HIDD, NPROJ);
    }
    {
        dim3 g((HIDD + 31) / 32, (IF + 31) / 32);
        transpose_round_kernel<<<g, dim3(32, 8)>>>(ow, (float*)p_owT, IF, HIDD);
    }

    // 1. in_proj GEMM: (8192 x 768) @ (768 x 3352)
    {
        dim3 grid((NPROJ + 127) / 128, TTOT / 128);
        tf32gemm_ldsm_kernel<<<grid, 256, smem_gemm>>>((const float*)p_hsr, (const float*)p_inwT,
                                                       (float*)p_zx, TTOT, NPROJ, HIDD);
    }
    // 2. conv + silu (float4)
    {
        dim3 grid(2, TTOT);
        conv_kernel<<<grid, 224>>>(cw, cb);
    }
    // 3. dt softplus
    dt_kernel<<<(TTOT * HH + 255) / 256, 256>>>(dtb);
    // 4. per-chunk cumsum of A*dt
    acum_kernel<<<BSZ * HH * CN, 256>>>(alog);
    // 5. local chunk states (tf32 mma + ldmatrix)
    chunkstate_mma_kernel<<<BSZ * CN * HH, 256, smem_cs>>>();
    // 6. inter-chunk recurrence (wide)
    recur_kernel<<<BSZ * HH * 32, 256>>>();
    // 7. Y_diag + Y_off + D residual (tf32 mma + ldmatrix)
    {
        dim3 grid(4, BSZ * CN * HH);
        ydiag_mma_kernel<<<grid, 256, smem_y>>>(Dp);
    }
    // 8. gated RMSNorm (writes tf32-rounded)
    gnorm_kernel<<<TTOT, 128>>>(nw);
    // 9. out_proj GEMM: (8192 x 1536) @ (1536 x 768) -> d_out
    {
        dim3 grid(HIDD / 128, TTOT / 128);
        tf32gemm_ldsm_kernel<<<grid, 256, smem_gemm>>>((const float*)p_y, (const float*)p_owT,
                                                       out, TTOT, HIDD, IF);
    }
}

// round 9
// speedup vs baseline: 1.3801x; 1.2766x over previous
#include <cuda_runtime.h>
#include <cuda_fp16.h>
#include <cuda_bf16.h>
#include <math.h>
#include <stdint.h>

// ---------------- problem constants ----------------
#define BSZ   2
#define LSEQ  4096
#define TTOT  8192          // BSZ*LSEQ
#define HIDD  768
#define IF    1536          // I
#define NST   128           // N
#define HH    24            // H
#define PP    64            // P
#define CSZ   256           // chunk size
#define CN    16            // LSEQ/CSZ
#define KC    4             // conv kernel
#define NPROJ 3352          // 2*(I+N)+H
#define XBCW  1792          // I+2N

// ---------------- scratch (static device globals; no allocs) ----------------
__device__ float  g_zx[TTOT * NPROJ];               // in_proj output (z | xBC | dt)
__device__ float  g_xc[TTOT * XBCW];                // conv+silu output
__device__ float  g_dt[TTOT * HH];                  // softplus(dt+bias)
__device__ float  g_ac[BSZ * HH * CN * CSZ];        // per-chunk inclusive cumsum of A*dt
__device__ float  g_ls[BSZ * CN * HH * PP * NST];   // local chunk states
__device__ float  g_ps[BSZ * CN * HH * PP * NST];   // prefix states entering chunk
__device__ float  g_y [TTOT * IF];                  // y fp32 (pre-norm)
__device__ __half g_yh [TTOT * IF];                 // y fp16 (post-norm, out_proj A)
__device__ __half g_hsh[TTOT * HIDD];               // hs in fp16
__device__ __half g_inwT[NPROJ * HIDD];             // in_proj_w^T, fp16
__device__ __half g_owT [HIDD * IF];                // out_proj_w^T, fp16

// ---------------- helpers ----------------
__device__ __forceinline__ float f2tf32(float x) {
    uint32_t r;
    asm("cvt.rna.tf32.f32 %0, %1;" : "=r"(r) : "f"(x));
    return __uint_as_float(r);
}
__device__ __forceinline__ uint32_t fu(float x) { return __float_as_uint(x); }

__device__ __forceinline__ void mma_tf32(float* c, uint32_t a0, uint32_t a1,
                                         uint32_t a2, uint32_t a3,
                                         uint32_t b0, uint32_t b1) {
    asm volatile(
        "mma.sync.aligned.m16n8k8.row.col.f32.tf32.tf32.f32 "
        "{%0,%1,%2,%3}, {%4,%5,%6,%7}, {%8,%9}, {%0,%1,%2,%3};\n"
        : "+f"(c[0]), "+f"(c[1]), "+f"(c[2]), "+f"(c[3])
        : "r"(a0), "r"(a1), "r"(a2), "r"(a3), "r"(b0), "r"(b1));
}
__device__ __forceinline__ void mma_f16(float* c, uint32_t a0, uint32_t a1,
                                        uint32_t a2, uint32_t a3,
                                        uint32_t b0, uint32_t b1) {
    asm volatile(
        "mma.sync.aligned.m16n8k16.row.col.f32.f16.f16.f32 "
        "{%0,%1,%2,%3}, {%4,%5,%6,%7}, {%8,%9}, {%0,%1,%2,%3};\n"
        : "+f"(c[0]), "+f"(c[1]), "+f"(c[2]), "+f"(c[3])
        : "r"(a0), "r"(a1), "r"(a2), "r"(a3), "r"(b0), "r"(b1));
}
__device__ __forceinline__ void ldsm_x4(uint32_t addr, uint32_t& r0, uint32_t& r1,
                                        uint32_t& r2, uint32_t& r3) {
    asm volatile("ldmatrix.sync.aligned.m8n8.x4.shared.b16 {%0,%1,%2,%3}, [%4];"
                 : "=r"(r0), "=r"(r1), "=r"(r2), "=r"(r3) : "r"(addr));
}
__device__ __forceinline__ void cpasync16(uint32_t daddr, const void* gaddr, bool pred) {
    int sz = pred ? 16 : 0;
    asm volatile("cp.async.cg.shared.global [%0], [%1], 16, %2;"
                 :: "r"(daddr), "l"(gaddr), "r"(sz));
}
#define CP_COMMIT()  asm volatile("cp.async.commit_group;")
#define CP_WAIT3()   asm volatile("cp.async.wait_group 3;")

// ================= FP16 GEMM: ldmatrix + cp.async, BK=16, 5 stages, BN=128 =================
// C(fp32) = A(MxK fp16) @ Bt^T, Bt is [N][K] fp16 row-major.
// 256 thr = 8 warps (warpM 2 x warpN 4), warp tile 64x32.
#define GSTH 24               // row stride in halves: 16 + 8 pad (48B rows, conflict-free)
#define STAGE_H (128 * GSTH)  // halves per matrix per stage
#define NSTAGE 5

__global__ __launch_bounds__(256, 2) void f16gemm_kernel(const __half* __restrict__ A,
                                                         const __half* __restrict__ Bt,
                                                         float* __restrict__ C,
                                                         int M, int N, int K) {
    extern __shared__ __half smh[];
    const int tid = threadIdx.x;
    const int lane = tid & 31;
    const int warpId = tid >> 5;
    const int gid = lane >> 2, tig = lane & 3;
    const int warpM = warpId & 1;
    const int warpN = warpId >> 1;
    const int rowBase = blockIdx.y * 128;
    const int colBase = blockIdx.x * 128;
    const int nk = K >> 4;

    uint32_t smBase = (uint32_t)__cvta_generic_to_shared(smh);

    // cp.async: row = tid>>1, 16B chunk = (tid&1) (8 halves)
    const int cpr = tid >> 1;
    const int cpc = (tid & 1) * 8;        // halves
    const int nB = colBase + cpr;
    const bool bOK = nB < N;
    const int nBc = bOK ? nB : 0;
    const uint32_t cpOffB = (uint32_t)(cpr * GSTH + cpc) * 2;   // bytes

    auto issue = [&](int kt, int stage) {
        int k0 = kt << 4;
        uint32_t sA = smBase + (uint32_t)(stage * 2 * STAGE_H) * 2 + cpOffB;
        uint32_t sB = smBase + (uint32_t)((stage * 2 + 1) * STAGE_H) * 2 + cpOffB;
        const __half* ga = &A[(size_t)(rowBase + cpr) * K + k0 + cpc];
        const __half* gb = &Bt[(size_t)nBc * K + k0 + cpc];
        cpasync16(sA, ga, true);
        cpasync16(sB, gb, bOK);
        CP_COMMIT();
    };

    // ldmatrix lane offsets (halves): lanes 0-7 rows r0-7 k-half0; 8-15 rows r8-15 k-half0;
    // 16-23 rows r0-7 k-half1; 24-31 rows r8-15 k-half1.
    const uint32_t lOff = (uint32_t)(((lane & 7) + ((lane >> 3) & 1) * 8) * GSTH + (lane >> 4) * 8);

    float acc[4][4][4];
#pragma unroll
    for (int mt = 0; mt < 4; mt++)
#pragma unroll
        for (int nt = 0; nt < 4; nt++)
#pragma unroll
            for (int e = 0; e < 4; e++) acc[mt][nt][e] = 0.f;

#pragma unroll
    for (int p = 0; p < NSTAGE - 1; p++)
        if (p < nk) issue(p, p);

    for (int kt = 0; kt < nk; kt++) {
        CP_WAIT3();
        __syncthreads();
        if (kt + NSTAGE - 1 < nk) issue(kt + NSTAGE - 1, (kt + NSTAGE - 1) % NSTAGE);

        int stage = kt % NSTAGE;
        uint32_t aBase = smBase + (uint32_t)(stage * 2 * STAGE_H) * 2;
        uint32_t bBase = smBase + (uint32_t)((stage * 2 + 1) * STAGE_H) * 2;

        // B fragments: 2 ldsm.x4 cover the warp's 32 columns
        uint32_t bfr[4][2];
#pragma unroll
        for (int pair = 0; pair < 2; pair++) {
            uint32_t addr = bBase + ((uint32_t)((warpN * 32 + pair * 16) * GSTH) + lOff) * 2;
            uint32_t r0, r1, r2, r3;
            ldsm_x4(addr, r0, r1, r2, r3);
            // r0 = n0-7/k0-7, r1 = n8-15/k0-7, r2 = n0-7/k8-15, r3 = n8-15/k8-15
            bfr[pair * 2][0] = r0; bfr[pair * 2][1] = r2;
            bfr[pair * 2 + 1][0] = r1; bfr[pair * 2 + 1][1] = r3;
        }
#pragma unroll
        for (int mt = 0; mt < 4; mt++) {
            uint32_t addr = aBase + ((uint32_t)((warpM * 64 + mt * 16) * GSTH) + lOff) * 2;
            uint32_t a0, a1, a2, a3;
            ldsm_x4(addr, a0, a1, a2, a3);   // a0 m0-7/k0-7, a1 m8-15/k0-7, a2 m0-7/k8-15, a3 m8-15/k8-15
#pragma unroll
            for (int nt = 0; nt < 4; nt++)
                mma_f16(acc[mt][nt], a0, a1, a2, a3, bfr[nt][0], bfr[nt][1]);
        }
    }

    // epilogue
#pragma unroll
    for (int mt = 0; mt < 4; mt++) {
        int r0 = rowBase + warpM * 64 + mt * 16 + gid;
#pragma unroll
        for (int nt = 0; nt < 4; nt++) {
            int c0 = colBase + warpN * 32 + nt * 8 + tig * 2;
            if (c0 < N)     C[(size_t)r0 * N + c0]           = acc[mt][nt][0];
            if (c0 + 1 < N) C[(size_t)r0 * N + c0 + 1]       = acc[mt][nt][1];
            if (c0 < N)     C[(size_t)(r0 + 8) * N + c0]     = acc[mt][nt][2];
            if (c0 + 1 < N) C[(size_t)(r0 + 8) * N + c0 + 1] = acc[mt][nt][3];
        }
    }
}

// ---------------- prep: round to fp16 / transpose+round ----------------
__global__ __launch_bounds__(256) void round_h_kernel(const float* __restrict__ src,
                                                      __half* __restrict__ dst, int n) {
    int i = blockIdx.x * 256 + threadIdx.x;
    if (i < n) dst[i] = __float2half(src[i]);
}

__global__ void transpose_round_h_kernel(const float* __restrict__ src,
                                         __half* __restrict__ dst, int R, int Cc) {
    __shared__ float t[32][33];
    int c0 = blockIdx.x * 32, r0 = blockIdx.y * 32;
    int x = c0 + threadIdx.x;
    for (int i = threadIdx.y; i < 32; i += 8) {
        int y = r0 + i;
        if (x < Cc && y < R) t[i][threadIdx.x] = src[(size_t)y * Cc + x];
    }
    __syncthreads();
    int xo = r0 + threadIdx.x;
    for (int i = threadIdx.y; i < 32; i += 8) {
        int yo = c0 + i;
        if (xo < R && yo < Cc) dst[(size_t)yo * R + xo] = __float2half(t[threadIdx.x][i]);
    }
}

// ---------------- conv1d (causal depthwise, K=4) + bias + silu, float4 ----------------
__global__ __launch_bounds__(224) void conv_kernel(const float* __restrict__ cw,
                                                   const float* __restrict__ cb) {
    int c4 = blockIdx.x * 224 + threadIdx.x;   // 0..447
    int ch = c4 * 4;
    int t  = blockIdx.y;
    int b  = t / LSEQ, l = t % LSEQ;
    float4 acc = *reinterpret_cast<const float4*>(&cb[ch]);
#pragma unroll
    for (int k = 0; k < KC; k++) {
        int lp = l - (KC - 1) + k;
        if (lp >= 0) {
            float4 xv = *reinterpret_cast<const float4*>(&g_zx[(size_t)(b * LSEQ + lp) * NPROJ + IF + ch]);
            float4 wv = *reinterpret_cast<const float4*>(&cw[k * XBCW + ch]);
            acc.x = fmaf(xv.x, wv.x, acc.x);
            acc.y = fmaf(xv.y, wv.y, acc.y);
            acc.z = fmaf(xv.z, wv.z, acc.z);
            acc.w = fmaf(xv.w, wv.w, acc.w);
        }
    }
    acc.x = acc.x / (1.f + expf(-acc.x));
    acc.y = acc.y / (1.f + expf(-acc.y));
    acc.z = acc.z / (1.f + expf(-acc.z));
    acc.w = acc.w / (1.f + expf(-acc.w));
    *reinterpret_cast<float4*>(&g_xc[(size_t)t * XBCW + ch]) = acc;
}

// ---------------- dt: softplus(dt_raw + bias), clip>=0 ----------------
__global__ __launch_bounds__(256) void dt_kernel(const float* __restrict__ dtb) {
    int idx = blockIdx.x * 256 + threadIdx.x;
    if (idx >= TTOT * HH) return;
    int t = idx / HH, h = idx % HH;
    float x = g_zx[(size_t)t * NPROJ + (NPROJ - HH) + h] + dtb[h];
    float sp = (x > 0.f) ? (x + log1pf(expf(-x))) : log1pf(expf(x));
    g_dt[idx] = fmaxf(sp, 0.f);
}

// ---------------- per-chunk inclusive cumsum of A*dt ----------------
__global__ __launch_bounds__(256) void acum_kernel(const float* __restrict__ alog) {
    int bx = blockIdx.x;
    int c  = bx % CN;
    int h  = (bx / CN) % HH;
    int b  = bx / (CN * HH);
    int s  = threadIdx.x;
    int t  = b * LSEQ + c * CSZ + s;
    float A = -expf(alog[h]);
    __shared__ float a[CSZ];
    a[s] = A * g_dt[(size_t)t * HH + h];
    __syncthreads();
    for (int off = 1; off < CSZ; off <<= 1) {
        float add = (s >= off) ? a[s - off] : 0.f;
        __syncthreads();
        a[s] += add;
        __syncthreads();
    }
    g_ac[(size_t)((b * HH + h) * CN + c) * CSZ + s] = a[s];
}

// ================= chunk state via TF32 mma + ldmatrix =================
#define CS_ST 68

__global__ __launch_bounds__(256) void chunkstate_mma_kernel() {
    extern __shared__ float sm[];
    float* As = sm;                    // 64 x 68
    float* Bs = sm + 64 * CS_ST;       // 128 x 68

    int bx = blockIdx.x;
    int h = bx % HH;
    int c = (bx / HH) % CN;
    int b = bx / (HH * CN);
    int tid = threadIdx.x, lane = tid & 31, warpId = tid >> 5;
    int gid = lane >> 2, tig = lane & 3;
    int warpM = warpId & 1, warpN = warpId >> 1;
    int acbase = ((b * HH + h) * CN + c) * CSZ;
    int tbase = b * LSEQ + c * CSZ;
    float Asum = g_ac[acbase + CSZ - 1];

    uint32_t smB = (uint32_t)__cvta_generic_to_shared(sm);
    uint32_t asB = smB;
    uint32_t bsB = smB + (uint32_t)(64 * CS_ST) * 4;
    const uint32_t aOff = (uint32_t)((lane & 15) * CS_ST + (lane >> 4) * 4);
    const uint32_t bOff = (uint32_t)(((lane >> 4) * 8 + (lane & 7)) * CS_ST + ((lane >> 3) & 1) * 4);

    float acc[2][4][4];
#pragma unroll
    for (int mt = 0; mt < 2; mt++)
#pragma unroll
        for (int nt = 0; nt < 4; nt++)
#pragma unroll
            for (int e = 0; e < 4; e++) acc[mt][nt][e] = 0.f;

    for (int kt = 0; kt < 4; kt++) {
        for (int i = tid; i < 64 * 64; i += 256) {
            int l = i >> 6, p = i & 63;
            int ts = tbase + kt * 64 + l;
            float v = g_xc[(size_t)ts * XBCW + h * PP + p] * g_dt[(size_t)ts * HH + h];
            As[p * CS_ST + l] = f2tf32(v);
        }
        for (int i = tid; i < 64 * 128; i += 256) {
            int l = i >> 7, n = i & 127;
            int ts = tbase + kt * 64 + l;
            float dec = expf(Asum - g_ac[acbase + kt * 64 + l]);
            Bs[n * CS_ST + l] = f2tf32(g_xc[(size_t)ts * XBCW + IF + n] * dec);
        }
        __syncthreads();
#pragma unroll
        for (int k8 = 0; k8 < 8; k8++) {
            int k0 = k8 * 8;
            uint32_t af[2][4];
#pragma unroll
            for (int mt = 0; mt < 2; mt++)
                ldsm_x4(asB + (uint32_t)((warpM * 32 + mt * 16) * CS_ST + k0 + aOff) * 4,
                        af[mt][0], af[mt][1], af[mt][2], af[mt][3]);
#pragma unroll
            for (int p2 = 0; p2 < 2; p2++) {
                uint32_t b0, b1, b2, b3;
                ldsm_x4(bsB + (uint32_t)((warpN * 32 + p2 * 16) * CS_ST + k0 + bOff) * 4, b0, b1, b2, b3);
#pragma unroll
                for (int mt = 0; mt < 2; mt++) {
                    mma_tf32(acc[mt][p2 * 2],     af[mt][0], af[mt][1], af[mt][2], af[mt][3], b0, b1);
                    mma_tf32(acc[mt][p2 * 2 + 1], af[mt][0], af[mt][1], af[mt][2], af[mt][3], b2, b3);
                }
            }
        }
        __syncthreads();
    }

    size_t base = ((size_t)((b * CN + c) * HH + h)) * PP * NST;
#pragma unroll
    for (int mt = 0; mt < 2; mt++) {
        int p0 = warpM * 32 + mt * 16 + gid;
#pragma unroll
        for (int nt = 0; nt < 4; nt++) {
            int n0 = warpN * 32 + nt * 8 + tig * 2;
            g_ls[base + (size_t)p0 * NST + n0]           = acc[mt][nt][0];
            g_ls[base + (size_t)p0 * NST + n0 + 1]       = acc[mt][nt][1];
            g_ls[base + (size_t)(p0 + 8) * NST + n0]     = acc[mt][nt][2];
            g_ls[base + (size_t)(p0 + 8) * NST + n0 + 1] = acc[mt][nt][3];
        }
    }
}

// ---------------- inter-chunk recurrence (1 element/thread) ----------------
__global__ __launch_bounds__(256) void recur_kernel() {
    int blk = blockIdx.x;            // BSZ*HH*32
    int seg = blk & 31;
    int bh  = blk >> 5;
    int b = bh / HH, h = bh % HH;
    int idx = seg * 256 + threadIdx.x;   // 0..8191
    float st = 0.f;
#pragma unroll
    for (int c = 0; c < CN; c++) {
        float es = expf(g_ac[(size_t)((b * HH + h) * CN + c) * CSZ + CSZ - 1]);
        size_t base = ((size_t)((b * CN + c) * HH + h)) * PP * NST;
        g_ps[base + idx] = st;
        st = fmaf(st, es, g_ls[base + idx]);
    }
}

// ================= Y via TF32 mma + ldmatrix =================
#define YD_CS 132
#define YD_XS 68
#define YD_GS 68

__global__ __launch_bounds__(256) void ydiag_mma_kernel(const float* __restrict__ Darr) {
    extern __shared__ float sm[];
    float* Cs  = sm;                        // 64 x 132
    float* Bst = Cs + 64 * YD_CS;           // 64 x 132
    float* Xs  = Bst + 64 * YD_CS;          // 64 x 68 (transposed [p][s])
    float* Gs  = Xs + 64 * YD_XS;           // 64 x 68
    float* aL  = Gs + 64 * YD_GS;
    float* aS  = aL + 64;

    int lt  = blockIdx.x;
    int bch = blockIdx.y;
    int h = bch % HH;
    int c = (bch / HH) % CN;
    int b = bch / (HH * CN);
    int tid = threadIdx.x, lane = tid & 31, warpId = tid >> 5;
    int gid = lane >> 2, tig = lane & 3;
    int m0 = (warpId & 3) * 16;
    int n0 = (warpId >> 2) * 32;
    int acbase = ((b * HH + h) * CN + c) * CSZ;
    int tbase = b * LSEQ + c * CSZ;

    uint32_t smB = (uint32_t)__cvta_generic_to_shared(sm);
    uint32_t csB  = smB;
    uint32_t bstB = smB + (uint32_t)(64 * YD_CS) * 4;
    uint32_t xsB  = bstB + (uint32_t)(64 * YD_CS) * 4;
    uint32_t gsB  = xsB + (uint32_t)(64 * YD_XS) * 4;

    const uint32_t aOff132 = (uint32_t)((lane & 15) * YD_CS + (lane >> 4) * 4);
    const uint32_t aOff68  = (uint32_t)((lane & 15) * YD_GS + (lane >> 4) * 4);
    const uint32_t bOff132 = (uint32_t)(((lane >> 4) * 8 + (lane & 7)) * YD_CS + ((lane >> 3) & 1) * 4);
    const uint32_t bOff68  = (uint32_t)(((lane >> 4) * 8 + (lane & 7)) * YD_XS + ((lane >> 3) & 1) * 4);

    for (int i = tid; i < 64 * 128; i += 256) {
        int l = i >> 7, n = i & 127;
        Cs[l * YD_CS + n] = f2tf32(g_xc[(size_t)(tbase + lt * 64 + l) * XBCW + IF + NST + n]);
    }
    if (tid < 64) aL[tid] = g_ac[acbase + lt * 64 + tid];

    float accD[4][4];
#pragma unroll
    for (int nt = 0; nt < 4; nt++)
#pragma unroll
        for (int e = 0; e < 4; e++) accD[nt][e] = 0.f;

    for (int st = 0; st <= lt; st++) {
        __syncthreads();
        for (int i = tid; i < 64 * 128; i += 256) {
            int s = i >> 7, n = i & 127;
            Bst[s * YD_CS + n] = f2tf32(g_xc[(size_t)(tbase + st * 64 + s) * XBCW + IF + n]);
        }
        for (int i = tid; i < 64 * 64; i += 256) {
            int s = i >> 6, p = i & 63;
            int ts = tbase + st * 64 + s;
            Xs[p * YD_XS + s] = f2tf32(g_xc[(size_t)ts * XBCW + h * PP + p] * g_dt[(size_t)ts * HH + h]);
        }
        if (tid < 64) aS[tid] = g_ac[acbase + st * 64 + tid];
        __syncthreads();

        // ---- G = C @ B^T (K = 128) ----
        float g4[4][4];
#pragma unroll
        for (int nt = 0; nt < 4; nt++)
#pragma unroll
            for (int e = 0; e < 4; e++) g4[nt][e] = 0.f;
#pragma unroll
        for (int k8 = 0; k8 < 16; k8++) {
            int k0 = k8 * 8;
            uint32_t a0, a1, a2, a3;
            ldsm_x4(csB + (uint32_t)(m0 * YD_CS + k0 + aOff132) * 4, a0, a1, a2, a3);
#pragma unroll
            for (int p2 = 0; p2 < 2; p2++) {
                uint32_t b0, b1, b2, b3;
                ldsm_x4(bstB + (uint32_t)((n0 + p2 * 16) * YD_CS + k0 + bOff132) * 4, b0, b1, b2, b3);
                mma_tf32(g4[p2 * 2],     a0, a1, a2, a3, b0, b1);
                mma_tf32(g4[p2 * 2 + 1], a0, a1, a2, a3, b2, b3);
            }
        }
        // ---- mask + decay in registers, spill to Gs ----
        {
            int lA = m0 + gid, lB = lA + 8;
            int glA = lt * 64 + lA, glB = glA + 8;
            float aLA = aL[lA], aLB = aL[lB];
#pragma unroll
            for (int nt = 0; nt < 4; nt++) {
                int s0 = n0 + nt * 8 + tig * 2;
                int gs0 = st * 64 + s0;
                float as0 = aS[s0], as1 = aS[s0 + 1];
                float v0 = (gs0     <= glA) ? g4[nt][0] * expf(aLA - as0) : 0.f;
                float v1 = (gs0 + 1 <= glA) ? g4[nt][1] * expf(aLA - as1) : 0.f;
                float v2 = (gs0     <= glB) ? g4[nt][2] * expf(aLB - as0) : 0.f;
                float v3 = (gs0 + 1 <= glB) ? g4[nt][3] * expf(aLB - as1) : 0.f;
                Gs[lA * YD_GS + s0]     = f2tf32(v0);
                Gs[lA * YD_GS + s0 + 1] = f2tf32(v1);
                Gs[lB * YD_GS + s0]     = f2tf32(v2);
                Gs[lB * YD_GS + s0 + 1] = f2tf32(v3);
            }
        }
        __syncthreads();
        // ---- acc += G @ Xd (K = 64), Xs is [p][s] ----
#pragma unroll
        for (int k8 = 0; k8 < 8; k8++) {
            int k0 = k8 * 8;
            uint32_t a0, a1, a2, a3;
            ldsm_x4(gsB + (uint32_t)(m0 * YD_GS + k0 + aOff68) * 4, a0, a1, a2, a3);
#pragma unroll
            for (int p2 = 0; p2 < 2; p2++) {
                uint32_t b0, b1, b2, b3;
                ldsm_x4(xsB + (uint32_t)((n0 + p2 * 16) * YD_XS + k0 + bOff68) * 4, b0, b1, b2, b3);
                mma_tf32(accD[p2 * 2],     a0, a1, a2, a3, b0, b1);
                mma_tf32(accD[p2 * 2 + 1], a0, a1, a2, a3, b2, b3);
            }
        }
    }

    // ---- off part: off = C @ S^T (K = 128) ----
    __syncthreads();
    {
        size_t sbase = ((size_t)((b * CN + c) * HH + h)) * PP * NST;
        for (int i = tid; i < 64 * 128; i += 256) {
            int p = i >> 7, n = i & 127;
            Bst[p * YD_CS + n] = f2tf32(g_ps[sbase + (size_t)p * NST + n]);
        }
    }
    __syncthreads();
    float off4[4][4];
#pragma unroll
    for (int nt = 0; nt < 4; nt++)
#pragma unroll
        for (int e = 0; e < 4; e++) off4[nt][e] = 0.f;
#pragma unroll
    for (int k8 = 0; k8 < 16; k8++) {
        int k0 = k8 * 8;
        uint32_t a0, a1, a2, a3;
        ldsm_x4(csB + (uint32_t)(m0 * YD_CS + k0 + aOff132) * 4, a0, a1, a2, a3);
#pragma unroll
        for (int p2 = 0; p2 < 2; p2++) {
            uint32_t b0, b1, b2, b3;
            ldsm_x4(bstB + (uint32_t)((n0 + p2 * 16) * YD_CS + k0 + bOff132) * 4, b0, b1, b2, b3);
            mma_tf32(off4[p2 * 2],     a0, a1, a2, a3, b0, b1);
            mma_tf32(off4[p2 * 2 + 1], a0, a1, a2, a3, b2, b3);
        }
    }

    // ---- epilogue: y = accD + exp(aL)*off + D*x ----
    {
        int lA = m0 + gid, lB = lA + 8;
        float e0 = expf(aL[lA]), e1 = expf(aL[lB]);
        float Dh = Darr[h];
        int tA = tbase + lt * 64 + lA;
        int tB = tbase + lt * 64 + lB;
#pragma unroll
        for (int nt = 0; nt < 4; nt++) {
            int p0 = n0 + nt * 8 + tig * 2;
            float xA0 = g_xc[(size_t)tA * XBCW + h * PP + p0];
            float xA1 = g_xc[(size_t)tA * XBCW + h * PP + p0 + 1];
            float xB0 = g_xc[(size_t)tB * XBCW + h * PP + p0];
            float xB1 = g_xc[(size_t)tB * XBCW + h * PP + p0 + 1];
            g_y[(size_t)tA * IF + h * PP + p0]     = accD[nt][0] + e0 * off4[nt][0] + Dh * xA0;
            g_y[(size_t)tA * IF + h * PP + p0 + 1] = accD[nt][1] + e0 * off4[nt][1] + Dh * xA1;
            g_y[(size_t)tB * IF + h * PP + p0]     = accD[nt][2] + e1 * off4[nt][2] + Dh * xB0;
            g_y[(size_t)tB * IF + h * PP + p0 + 1] = accD[nt][3] + e1 * off4[nt][3] + Dh * xB1;
        }
    }
}

// ---------------- gated RMSNorm (float4 in, fp16 out) ----------------
__global__ __launch_bounds__(128) void gnorm_kernel(const float* __restrict__ nw) {
    int t = blockIdx.x;
    int tid = threadIdx.x;
    float4 v[3];
    float ss = 0.f;
#pragma unroll
    for (int k = 0; k < 3; k++) {
        int i = (tid + k * 128) * 4;
        float4 y = *reinterpret_cast<const float4*>(&g_y[(size_t)t * IF + i]);
        float4 z = *reinterpret_cast<const float4*>(&g_zx[(size_t)t * NPROJ + i]);
        float x0 = y.x * (z.x / (1.f + expf(-z.x)));
        float x1 = y.y * (z.y / (1.f + expf(-z.y)));
        float x2 = y.z * (z.z / (1.f + expf(-z.z)));
        float x3 = y.w * (z.w / (1.f + expf(-z.w)));
        v[k] = make_float4(x0, x1, x2, x3);
        ss += x0 * x0 + x1 * x1 + x2 * x2 + x3 * x3;
    }
    __shared__ float red[128];
    __shared__ float s_scale;
    red[tid] = ss;
    __syncthreads();
    for (int o = 64; o > 0; o >>= 1) {
        if (tid < o) red[tid] += red[tid + o];
        __syncthreads();
    }
    if (tid == 0) s_scale = rsqrtf(red[0] / (float)IF + 1e-5f);
    __syncthreads();
    float sc = s_scale;
#pragma unroll
    for (int k = 0; k < 3; k++) {
        int i = (tid + k * 128) * 4;
        float4 w = *reinterpret_cast<const float4*>(&nw[i]);
        __half2 h0 = __floats2half2_rn(v[k].x * sc * w.x, v[k].y * sc * w.y);
        __half2 h1 = __floats2half2_rn(v[k].z * sc * w.z, v[k].w * sc * w.w);
        *reinterpret_cast<__half2*>(&g_yh[(size_t)t * IF + i])     = h0;
        *reinterpret_cast<__half2*>(&g_yh[(size_t)t * IF + i + 2]) = h1;
    }
}

// ---------------- host launcher ----------------
extern "C" void kernel_launch(void* const* d_in, const int* in_sizes, int n_in,
                              void* d_out, int out_size) {
    const float* hs   = (const float*)d_in[0];
    const float* inw  = (const float*)d_in[1];
    const float* cw   = (const float*)d_in[2];
    const float* cb   = (const float*)d_in[3];
    const float* dtb  = (const float*)d_in[4];
    const float* alog = (const float*)d_in[5];
    const float* Dp   = (const float*)d_in[6];
    const float* nw   = (const float*)d_in[7];
    const float* ow   = (const float*)d_in[8];
    float* out = (float*)d_out;

    void *p_zx = nullptr, *p_yh = nullptr, *p_hsh = nullptr, *p_inwT = nullptr, *p_owT = nullptr;
    cudaGetSymbolAddress(&p_zx, g_zx);
    cudaGetSymbolAddress(&p_yh, g_yh);
    cudaGetSymbolAddress(&p_hsh, g_hsh);
    cudaGetSymbolAddress(&p_inwT, g_inwT);
    cudaGetSymbolAddress(&p_owT, g_owT);

    int smem_gemm = NSTAGE * 2 * STAGE_H * 2;                                // 61440
    int smem_cs = (64 * CS_ST + 128 * CS_ST) * 4;                            // 52224
    int smem_y  = (64 * YD_CS * 2 + 64 * YD_XS + 64 * YD_GS + 128) * 4;      // ~103.4KB
    cudaFuncSetAttribute(f16gemm_kernel, cudaFuncAttributeMaxDynamicSharedMemorySize, smem_gemm);
    cudaFuncSetAttribute(chunkstate_mma_kernel, cudaFuncAttributeMaxDynamicSharedMemorySize, smem_cs);
    cudaFuncSetAttribute(ydiag_mma_kernel, cudaFuncAttributeMaxDynamicSharedMemorySize, smem_y);

    // 0. prep: hs -> fp16; weights transpose -> fp16
    round_h_kernel<<<(TTOT * HIDD + 255) / 256, 256>>>(hs, (__half*)p_hsh, TTOT * HIDD);
    {
        dim3 g((NPROJ + 31) / 32, (HIDD + 31) / 32);
        transpose_round_h_kernel<<<g, dim3(32, 8)>>>(inw, (__half*)p_inwT, HIDD, NPROJ);
    }
    {
        dim3 g((HIDD + 31) / 32, (IF + 31) / 32);
        transpose_round_h_kernel<<<g, dim3(32, 8)>>>(ow, (__half*)p_owT, IF, HIDD);
    }

    // 1. in_proj GEMM (fp16 mma): (8192 x 768) @ (768 x 3352)
    {
        dim3 grid((NPROJ + 127) / 128, TTOT / 128);
        f16gemm_kernel<<<grid, 256, smem_gemm>>>((const __half*)p_hsh, (const __half*)p_inwT,
                                                 (float*)p_zx, TTOT, NPROJ, HIDD);
    }
    // 2. conv + silu (float4)
    {
        dim3 grid(2, TTOT);
        conv_kernel<<<grid, 224>>>(cw, cb);
    }
    // 3. dt softplus
    dt_kernel<<<(TTOT * HH + 255) / 256, 256>>>(dtb);
    // 4. per-chunk cumsum of A*dt
    acum_kernel<<<BSZ * HH * CN, 256>>>(alog);
    // 5. local chunk states (tf32 mma + ldmatrix)
    chunkstate_mma_kernel<<<BSZ * CN * HH, 256, smem_cs>>>();
    // 6. inter-chunk recurrence (wide)
    recur_kernel<<<BSZ * HH * 32, 256>>>();
    // 7. Y_diag + Y_off + D residual (tf32 mma + ldmatrix)
    {
        dim3 grid(4, BSZ * CN * HH);
        ydiag_mma_kernel<<<grid, 256, smem_y>>>(Dp);
    }
    // 8. gated RMSNorm (writes fp16)
    gnorm_kernel<<<TTOT, 128>>>(nw);
    // 9. out_proj GEMM (fp16 mma): (8192 x 1536) @ (1536 x 768) -> d_out
    {
        dim3 grid(HIDD / 128, TTOT / 128);
        f16gemm_kernel<<<grid, 256, smem_gemm>>>((const __half*)p_yh, (const __half*)p_owT,
                                                 out, TTOT, HIDD, IF);
    }
}

// round 10
// speedup vs baseline: 1.6687x; 1.2091x over previous
#include <cuda_runtime.h>
#include <cuda_fp16.h>
#include <cuda_bf16.h>
#include <math.h>
#include <stdint.h>

// ---------------- problem constants ----------------
#define BSZ   2
#define LSEQ  4096
#define TTOT  8192          // BSZ*LSEQ
#define HIDD  768
#define IF    1536          // I
#define NST   128           // N
#define HH    24            // H
#define PP    64            // P
#define CSZ   256           // chunk size
#define CN    16            // LSEQ/CSZ
#define KC    4             // conv kernel
#define NPROJ 3352          // 2*(I+N)+H
#define XBCW  1792          // I+2N

// ---------------- scratch (static device globals; no allocs) ----------------
__device__ float  g_zx[TTOT * NPROJ];               // in_proj output (z | xBC | dt)
__device__ float  g_xc[TTOT * XBCW];                // conv+silu output
__device__ float  g_dt[TTOT * HH];                  // softplus(dt+bias)
__device__ float  g_ac[BSZ * HH * CN * CSZ];        // per-chunk inclusive cumsum of A*dt
__device__ float  g_ls[BSZ * CN * HH * PP * NST];   // local chunk states
__device__ float  g_ps[BSZ * CN * HH * PP * NST];   // prefix states entering chunk
__device__ float  g_y [TTOT * IF];                  // y fp32 (pre-norm)
__device__ __half g_yh [TTOT * IF];                 // y fp16 (post-norm, out_proj A)
__device__ __half g_hsh[TTOT * HIDD];               // hs in fp16
__device__ __half g_inwT[NPROJ * HIDD];             // in_proj_w^T, fp16
__device__ __half g_owT [HIDD * IF];                // out_proj_w^T, fp16

// ---------------- helpers ----------------
__device__ __forceinline__ uint32_t fu(float x) { return __float_as_uint(x); }

__device__ __forceinline__ void mma_f16(float* c, uint32_t a0, uint32_t a1,
                                        uint32_t a2, uint32_t a3,
                                        uint32_t b0, uint32_t b1) {
    asm volatile(
        "mma.sync.aligned.m16n8k16.row.col.f32.f16.f16.f32 "
        "{%0,%1,%2,%3}, {%4,%5,%6,%7}, {%8,%9}, {%0,%1,%2,%3};\n"
        : "+f"(c[0]), "+f"(c[1]), "+f"(c[2]), "+f"(c[3])
        : "r"(a0), "r"(a1), "r"(a2), "r"(a3), "r"(b0), "r"(b1));
}
__device__ __forceinline__ void ldsm_x4(uint32_t addr, uint32_t& r0, uint32_t& r1,
                                        uint32_t& r2, uint32_t& r3) {
    asm volatile("ldmatrix.sync.aligned.m8n8.x4.shared.b16 {%0,%1,%2,%3}, [%4];"
                 : "=r"(r0), "=r"(r1), "=r"(r2), "=r"(r3) : "r"(addr));
}
__device__ __forceinline__ void cpasync16(uint32_t daddr, const void* gaddr, bool pred) {
    int sz = pred ? 16 : 0;
    asm volatile("cp.async.cg.shared.global [%0], [%1], 16, %2;"
                 :: "r"(daddr), "l"(gaddr), "r"(sz));
}
#define CP_COMMIT()  asm volatile("cp.async.commit_group;")
#define CP_WAIT3()   asm volatile("cp.async.wait_group 3;")

// fp16 ldmatrix lane offset (in halves) for a [rows][k] tile with row stride S halves:
// lanes 0-7 rows0-7/k0, 8-15 rows8-15/k0, 16-23 rows0-7/k8, 24-31 rows8-15/k8
#define LDSM_OFF_H(S) ((uint32_t)(((lane & 7) + ((lane >> 3) & 1) * 8) * (S) + (lane >> 4) * 8))

// ================= FP16 GEMM: ldmatrix + cp.async, BK=16, 5 stages, BN=128 =================
#define GSTH 24               // row stride in halves: 16 + 8 pad
#define STAGE_H (128 * GSTH)  // halves per matrix per stage
#define NSTAGE 5

__global__ __launch_bounds__(256, 2) void f16gemm_kernel(const __half* __restrict__ A,
                                                         const __half* __restrict__ Bt,
                                                         float* __restrict__ C,
                                                         int M, int N, int K) {
    extern __shared__ __half smh[];
    const int tid = threadIdx.x;
    const int lane = tid & 31;
    const int warpId = tid >> 5;
    const int gid = lane >> 2, tig = lane & 3;
    const int warpM = warpId & 1;
    const int warpN = warpId >> 1;
    const int rowBase = blockIdx.y * 128;
    const int colBase = blockIdx.x * 128;
    const int nk = K >> 4;

    uint32_t smBase = (uint32_t)__cvta_generic_to_shared(smh);

    const int cpr = tid >> 1;
    const int cpc = (tid & 1) * 8;
    const int nB = colBase + cpr;
    const bool bOK = nB < N;
    const int nBc = bOK ? nB : 0;
    const uint32_t cpOffB = (uint32_t)(cpr * GSTH + cpc) * 2;

    auto issue = [&](int kt, int stage) {
        int k0 = kt << 4;
        uint32_t sA = smBase + (uint32_t)(stage * 2 * STAGE_H) * 2 + cpOffB;
        uint32_t sB = smBase + (uint32_t)((stage * 2 + 1) * STAGE_H) * 2 + cpOffB;
        const __half* ga = &A[(size_t)(rowBase + cpr) * K + k0 + cpc];
        const __half* gb = &Bt[(size_t)nBc * K + k0 + cpc];
        cpasync16(sA, ga, true);
        cpasync16(sB, gb, bOK);
        CP_COMMIT();
    };

    const uint32_t lOff = LDSM_OFF_H(GSTH);

    float acc[4][4][4];
#pragma unroll
    for (int mt = 0; mt < 4; mt++)
#pragma unroll
        for (int nt = 0; nt < 4; nt++)
#pragma unroll
            for (int e = 0; e < 4; e++) acc[mt][nt][e] = 0.f;

#pragma unroll
    for (int p = 0; p < NSTAGE - 1; p++)
        if (p < nk) issue(p, p);

    for (int kt = 0; kt < nk; kt++) {
        CP_WAIT3();
        __syncthreads();
        if (kt + NSTAGE - 1 < nk) issue(kt + NSTAGE - 1, (kt + NSTAGE - 1) % NSTAGE);

        int stage = kt % NSTAGE;
        uint32_t aBase = smBase + (uint32_t)(stage * 2 * STAGE_H) * 2;
        uint32_t bBase = smBase + (uint32_t)((stage * 2 + 1) * STAGE_H) * 2;

        uint32_t bfr[4][2];
#pragma unroll
        for (int pair = 0; pair < 2; pair++) {
            uint32_t addr = bBase + ((uint32_t)((warpN * 32 + pair * 16) * GSTH) + lOff) * 2;
            uint32_t r0, r1, r2, r3;
            ldsm_x4(addr, r0, r1, r2, r3);
            bfr[pair * 2][0] = r0; bfr[pair * 2][1] = r2;
            bfr[pair * 2 + 1][0] = r1; bfr[pair * 2 + 1][1] = r3;
        }
#pragma unroll
        for (int mt = 0; mt < 4; mt++) {
            uint32_t addr = aBase + ((uint32_t)((warpM * 64 + mt * 16) * GSTH) + lOff) * 2;
            uint32_t a0, a1, a2, a3;
            ldsm_x4(addr, a0, a1, a2, a3);
#pragma unroll
            for (int nt = 0; nt < 4; nt++)
                mma_f16(acc[mt][nt], a0, a1, a2, a3, bfr[nt][0], bfr[nt][1]);
        }
    }

#pragma unroll
    for (int mt = 0; mt < 4; mt++) {
        int r0 = rowBase + warpM * 64 + mt * 16 + gid;
#pragma unroll
        for (int nt = 0; nt < 4; nt++) {
            int c0 = colBase + warpN * 32 + nt * 8 + tig * 2;
            if (c0 < N)     C[(size_t)r0 * N + c0]           = acc[mt][nt][0];
            if (c0 + 1 < N) C[(size_t)r0 * N + c0 + 1]       = acc[mt][nt][1];
            if (c0 < N)     C[(size_t)(r0 + 8) * N + c0]     = acc[mt][nt][2];
            if (c0 + 1 < N) C[(size_t)(r0 + 8) * N + c0 + 1] = acc[mt][nt][3];
        }
    }
}

// ---------------- prep ----------------
__global__ __launch_bounds__(256) void round_h_kernel(const float* __restrict__ src,
                                                      __half* __restrict__ dst, int n) {
    int i = blockIdx.x * 256 + threadIdx.x;
    if (i < n) dst[i] = __float2half(src[i]);
}

__global__ void transpose_round_h_kernel(const float* __restrict__ src,
                                         __half* __restrict__ dst, int R, int Cc) {
    __shared__ float t[32][33];
    int c0 = blockIdx.x * 32, r0 = blockIdx.y * 32;
    int x = c0 + threadIdx.x;
    for (int i = threadIdx.y; i < 32; i += 8) {
        int y = r0 + i;
        if (x < Cc && y < R) t[i][threadIdx.x] = src[(size_t)y * Cc + x];
    }
    __syncthreads();
    int xo = r0 + threadIdx.x;
    for (int i = threadIdx.y; i < 32; i += 8) {
        int yo = c0 + i;
        if (xo < R && yo < Cc) dst[(size_t)yo * R + xo] = __float2half(t[threadIdx.x][i]);
    }
}

// ---------------- conv1d + bias + silu, float4 ----------------
__global__ __launch_bounds__(224) void conv_kernel(const float* __restrict__ cw,
                                                   const float* __restrict__ cb) {
    int c4 = blockIdx.x * 224 + threadIdx.x;
    int ch = c4 * 4;
    int t  = blockIdx.y;
    int b  = t / LSEQ, l = t % LSEQ;
    float4 acc = *reinterpret_cast<const float4*>(&cb[ch]);
#pragma unroll
    for (int k = 0; k < KC; k++) {
        int lp = l - (KC - 1) + k;
        if (lp >= 0) {
            float4 xv = *reinterpret_cast<const float4*>(&g_zx[(size_t)(b * LSEQ + lp) * NPROJ + IF + ch]);
            float4 wv = *reinterpret_cast<const float4*>(&cw[k * XBCW + ch]);
            acc.x = fmaf(xv.x, wv.x, acc.x);
            acc.y = fmaf(xv.y, wv.y, acc.y);
            acc.z = fmaf(xv.z, wv.z, acc.z);
            acc.w = fmaf(xv.w, wv.w, acc.w);
        }
    }
    acc.x = acc.x / (1.f + expf(-acc.x));
    acc.y = acc.y / (1.f + expf(-acc.y));
    acc.z = acc.z / (1.f + expf(-acc.z));
    acc.w = acc.w / (1.f + expf(-acc.w));
    *reinterpret_cast<float4*>(&g_xc[(size_t)t * XBCW + ch]) = acc;
}

// ---------------- dt softplus ----------------
__global__ __launch_bounds__(256) void dt_kernel(const float* __restrict__ dtb) {
    int idx = blockIdx.x * 256 + threadIdx.x;
    if (idx >= TTOT * HH) return;
    int t = idx / HH, h = idx % HH;
    float x = g_zx[(size_t)t * NPROJ + (NPROJ - HH) + h] + dtb[h];
    float sp = (x > 0.f) ? (x + log1pf(expf(-x))) : log1pf(expf(x));
    g_dt[idx] = fmaxf(sp, 0.f);
}

// ---------------- per-chunk cumsum of A*dt ----------------
__global__ __launch_bounds__(256) void acum_kernel(const float* __restrict__ alog) {
    int bx = blockIdx.x;
    int c  = bx % CN;
    int h  = (bx / CN) % HH;
    int b  = bx / (CN * HH);
    int s  = threadIdx.x;
    int t  = b * LSEQ + c * CSZ + s;
    float A = -expf(alog[h]);
    __shared__ float a[CSZ];
    a[s] = A * g_dt[(size_t)t * HH + h];
    __syncthreads();
    for (int off = 1; off < CSZ; off <<= 1) {
        float add = (s >= off) ? a[s - off] : 0.f;
        __syncthreads();
        a[s] += add;
        __syncthreads();
    }
    g_ac[(size_t)((b * HH + h) * CN + c) * CSZ + s] = a[s];
}

// ================= chunk state via FP16 mma + ldmatrix =================
// As [p][l] stride 72 halves; Bs [n][l] stride 72 halves. K per tile = 64 -> 4 k16 steps.
#define CS_SH 72

__global__ __launch_bounds__(256) void chunkstate_mma_kernel() {
    extern __shared__ __half smh[];
    __half* As = smh;                    // 64 x 72
    __half* Bs = smh + 64 * CS_SH;       // 128 x 72

    int bx = blockIdx.x;
    int h = bx % HH;
    int c = (bx / HH) % CN;
    int b = bx / (HH * CN);
    int tid = threadIdx.x, lane = tid & 31, warpId = tid >> 5;
    int gid = lane >> 2, tig = lane & 3;
    int warpM = warpId & 1, warpN = warpId >> 1;
    int acbase = ((b * HH + h) * CN + c) * CSZ;
    int tbase = b * LSEQ + c * CSZ;
    float Asum = g_ac[acbase + CSZ - 1];

    uint32_t smB = (uint32_t)__cvta_generic_to_shared(smh);
    uint32_t asB = smB;
    uint32_t bsB = smB + (uint32_t)(64 * CS_SH) * 2;
    const uint32_t lOff = LDSM_OFF_H(CS_SH);

    float acc[2][4][4];
#pragma unroll
    for (int mt = 0; mt < 2; mt++)
#pragma unroll
        for (int nt = 0; nt < 4; nt++)
#pragma unroll
            for (int e = 0; e < 4; e++) acc[mt][nt][e] = 0.f;

    for (int kt = 0; kt < 4; kt++) {
        for (int i = tid; i < 64 * 64; i += 256) {
            int l = i >> 6, p = i & 63;
            int ts = tbase + kt * 64 + l;
            float v = g_xc[(size_t)ts * XBCW + h * PP + p] * g_dt[(size_t)ts * HH + h];
            As[p * CS_SH + l] = __float2half(v);
        }
        for (int i = tid; i < 64 * 128; i += 256) {
            int l = i >> 7, n = i & 127;
            int ts = tbase + kt * 64 + l;
            float dec = expf(Asum - g_ac[acbase + kt * 64 + l]);
            Bs[n * CS_SH + l] = __float2half(g_xc[(size_t)ts * XBCW + IF + n] * dec);
        }
        __syncthreads();
#pragma unroll
        for (int k16 = 0; k16 < 4; k16++) {
            int k0 = k16 * 16;
            uint32_t af[2][4];
#pragma unroll
            for (int mt = 0; mt < 2; mt++)
                ldsm_x4(asB + ((uint32_t)((warpM * 32 + mt * 16) * CS_SH + k0) + lOff) * 2,
                        af[mt][0], af[mt][1], af[mt][2], af[mt][3]);
#pragma unroll
            for (int p2 = 0; p2 < 2; p2++) {
                uint32_t r0, r1, r2, r3;
                ldsm_x4(bsB + ((uint32_t)((warpN * 32 + p2 * 16) * CS_SH + k0) + lOff) * 2, r0, r1, r2, r3);
#pragma unroll
                for (int mt = 0; mt < 2; mt++) {
                    mma_f16(acc[mt][p2 * 2],     af[mt][0], af[mt][1], af[mt][2], af[mt][3], r0, r2);
                    mma_f16(acc[mt][p2 * 2 + 1], af[mt][0], af[mt][1], af[mt][2], af[mt][3], r1, r3);
                }
            }
        }
        __syncthreads();
    }

    size_t base = ((size_t)((b * CN + c) * HH + h)) * PP * NST;
#pragma unroll
    for (int mt = 0; mt < 2; mt++) {
        int p0 = warpM * 32 + mt * 16 + gid;
#pragma unroll
        for (int nt = 0; nt < 4; nt++) {
            int n0 = warpN * 32 + nt * 8 + tig * 2;
            g_ls[base + (size_t)p0 * NST + n0]           = acc[mt][nt][0];
            g_ls[base + (size_t)p0 * NST + n0 + 1]       = acc[mt][nt][1];
            g_ls[base + (size_t)(p0 + 8) * NST + n0]     = acc[mt][nt][2];
            g_ls[base + (size_t)(p0 + 8) * NST + n0 + 1] = acc[mt][nt][3];
        }
    }
}

// ---------------- inter-chunk recurrence ----------------
__global__ __launch_bounds__(256) void recur_kernel() {
    int blk = blockIdx.x;
    int seg = blk & 31;
    int bh  = blk >> 5;
    int b = bh / HH, h = bh % HH;
    int idx = seg * 256 + threadIdx.x;
    float st = 0.f;
#pragma unroll
    for (int c = 0; c < CN; c++) {
        float es = expf(g_ac[(size_t)((b * HH + h) * CN + c) * CSZ + CSZ - 1]);
        size_t base = ((size_t)((b * CN + c) * HH + h)) * PP * NST;
        g_ps[base + idx] = st;
        st = fmaf(st, es, g_ls[base + idx]);
    }
}

// ================= Y via FP16 mma + ldmatrix =================
// Cs [l][n] 136h; Bst [s|p][n] 136h; Xs [p][s] 72h; Gs [l][s] 72h; aL/aS fp32 after.
#define YH_CS 136
#define YH_XS 72
#define YH_GS 72
#define YD_HALves (64 * YH_CS * 2 + 64 * YH_XS + 64 * YH_GS)

__global__ __launch_bounds__(256) void ydiag_mma_kernel(const float* __restrict__ Darr) {
    extern __shared__ __half smh[];
    __half* Cs  = smh;                        // 64 x 136
    __half* Bst = Cs + 64 * YH_CS;            // 64 x 136
    __half* Xs  = Bst + 64 * YH_CS;           // 64 x 72 ([p][s])
    __half* Gs  = Xs + 64 * YH_XS;            // 64 x 72
    float* aL  = reinterpret_cast<float*>(Gs + 64 * YH_GS);
    float* aS  = aL + 64;

    int lt  = blockIdx.x;
    int bch = blockIdx.y;
    int h = bch % HH;
    int c = (bch / HH) % CN;
    int b = bch / (HH * CN);
    int tid = threadIdx.x, lane = tid & 31, warpId = tid >> 5;
    int gid = lane >> 2, tig = lane & 3;
    int m0 = (warpId & 3) * 16;
    int n0 = (warpId >> 2) * 32;
    int acbase = ((b * HH + h) * CN + c) * CSZ;
    int tbase = b * LSEQ + c * CSZ;

    uint32_t smB = (uint32_t)__cvta_generic_to_shared(smh);
    uint32_t csB  = smB;
    uint32_t bstB = smB + (uint32_t)(64 * YH_CS) * 2;
    uint32_t xsB  = bstB + (uint32_t)(64 * YH_CS) * 2;
    uint32_t gsB  = xsB + (uint32_t)(64 * YH_XS) * 2;

    const uint32_t lOff136 = LDSM_OFF_H(YH_CS);
    const uint32_t lOff72  = LDSM_OFF_H(YH_XS);

    for (int i = tid; i < 64 * 128; i += 256) {
        int l = i >> 7, n = i & 127;
        Cs[l * YH_CS + n] = __float2half(g_xc[(size_t)(tbase + lt * 64 + l) * XBCW + IF + NST + n]);
    }
    if (tid < 64) aL[tid] = g_ac[acbase + lt * 64 + tid];

    float accD[4][4];
#pragma unroll
    for (int nt = 0; nt < 4; nt++)
#pragma unroll
        for (int e = 0; e < 4; e++) accD[nt][e] = 0.f;

    for (int st = 0; st <= lt; st++) {
        __syncthreads();
        for (int i = tid; i < 64 * 128; i += 256) {
            int s = i >> 7, n = i & 127;
            Bst[s * YH_CS + n] = __float2half(g_xc[(size_t)(tbase + st * 64 + s) * XBCW + IF + n]);
        }
        for (int i = tid; i < 64 * 64; i += 256) {
            int s = i >> 6, p = i & 63;
            int ts = tbase + st * 64 + s;
            Xs[p * YH_XS + s] = __float2half(g_xc[(size_t)ts * XBCW + h * PP + p] * g_dt[(size_t)ts * HH + h]);
        }
        if (tid < 64) aS[tid] = g_ac[acbase + st * 64 + tid];
        __syncthreads();

        // ---- G = C @ B^T (K = 128 -> 8 k16 steps) ----
        float g4[4][4];
#pragma unroll
        for (int nt = 0; nt < 4; nt++)
#pragma unroll
            for (int e = 0; e < 4; e++) g4[nt][e] = 0.f;
#pragma unroll
        for (int k16 = 0; k16 < 8; k16++) {
            int k0 = k16 * 16;
            uint32_t a0, a1, a2, a3;
            ldsm_x4(csB + ((uint32_t)(m0 * YH_CS + k0) + lOff136) * 2, a0, a1, a2, a3);
#pragma unroll
            for (int p2 = 0; p2 < 2; p2++) {
                uint32_t r0, r1, r2, r3;
                ldsm_x4(bstB + ((uint32_t)((n0 + p2 * 16) * YH_CS + k0) + lOff136) * 2, r0, r1, r2, r3);
                mma_f16(g4[p2 * 2],     a0, a1, a2, a3, r0, r2);
                mma_f16(g4[p2 * 2 + 1], a0, a1, a2, a3, r1, r3);
            }
        }
        // ---- mask + decay in registers, spill to Gs (fp16) ----
        {
            int lA = m0 + gid, lB = lA + 8;
            int glA = lt * 64 + lA, glB = glA + 8;
            float aLA = aL[lA], aLB = aL[lB];
#pragma unroll
            for (int nt = 0; nt < 4; nt++) {
                int s0 = n0 + nt * 8 + tig * 2;
                int gs0 = st * 64 + s0;
                float as0 = aS[s0], as1 = aS[s0 + 1];
                float v0 = (gs0     <= glA) ? g4[nt][0] * expf(aLA - as0) : 0.f;
                float v1 = (gs0 + 1 <= glA) ? g4[nt][1] * expf(aLA - as1) : 0.f;
                float v2 = (gs0     <= glB) ? g4[nt][2] * expf(aLB - as0) : 0.f;
                float v3 = (gs0 + 1 <= glB) ? g4[nt][3] * expf(aLB - as1) : 0.f;
                *reinterpret_cast<__half2*>(&Gs[lA * YH_GS + s0]) = __floats2half2_rn(v0, v1);
                *reinterpret_cast<__half2*>(&Gs[lB * YH_GS + s0]) = __floats2half2_rn(v2, v3);
            }
        }
        __syncthreads();
        // ---- acc += G @ Xd (K = 64 -> 4 k16 steps), Xs is [p][s] ----
#pragma unroll
        for (int k16 = 0; k16 < 4; k16++) {
            int k0 = k16 * 16;
            uint32_t a0, a1, a2, a3;
            ldsm_x4(gsB + ((uint32_t)(m0 * YH_GS + k0) + lOff72) * 2, a0, a1, a2, a3);
#pragma unroll
            for (int p2 = 0; p2 < 2; p2++) {
                uint32_t r0, r1, r2, r3;
                ldsm_x4(xsB + ((uint32_t)((n0 + p2 * 16) * YH_XS + k0) + lOff72) * 2, r0, r1, r2, r3);
                mma_f16(accD[p2 * 2],     a0, a1, a2, a3, r0, r2);
                mma_f16(accD[p2 * 2 + 1], a0, a1, a2, a3, r1, r3);
            }
        }
    }

    // ---- off part: off = C @ S^T (K = 128) ----
    __syncthreads();
    {
        size_t sbase = ((size_t)((b * CN + c) * HH + h)) * PP * NST;
        for (int i = tid; i < 64 * 128; i += 256) {
            int p = i >> 7, n = i & 127;
            Bst[p * YH_CS + n] = __float2half(g_ps[sbase + (size_t)p * NST + n]);
        }
    }
    __syncthreads();
    float off4[4][4];
#pragma unroll
    for (int nt = 0; nt < 4; nt++)
#pragma unroll
        for (int e = 0; e < 4; e++) off4[nt][e] = 0.f;
#pragma unroll
    for (int k16 = 0; k16 < 8; k16++) {
        int k0 = k16 * 16;
        uint32_t a0, a1, a2, a3;
        ldsm_x4(csB + ((uint32_t)(m0 * YH_CS + k0) + lOff136) * 2, a0, a1, a2, a3);
#pragma unroll
        for (int p2 = 0; p2 < 2; p2++) {
            uint32_t r0, r1, r2, r3;
            ldsm_x4(bstB + ((uint32_t)((n0 + p2 * 16) * YH_CS + k0) + lOff136) * 2, r0, r1, r2, r3);
            mma_f16(off4[p2 * 2],     a0, a1, a2, a3, r0, r2);
            mma_f16(off4[p2 * 2 + 1], a0, a1, a2, a3, r1, r3);
        }
    }

    // ---- epilogue: y = accD + exp(aL)*off + D*x ----
    {
        int lA = m0 + gid, lB = lA + 8;
        float e0 = expf(aL[lA]), e1 = expf(aL[lB]);
        float Dh = Darr[h];
        int tA = tbase + lt * 64 + lA;
        int tB = tbase + lt * 64 + lB;
#pragma unroll
        for (int nt = 0; nt < 4; nt++) {
            int p0 = n0 + nt * 8 + tig * 2;
            float xA0 = g_xc[(size_t)tA * XBCW + h * PP + p0];
            float xA1 = g_xc[(size_t)tA * XBCW + h * PP + p0 + 1];
            float xB0 = g_xc[(size_t)tB * XBCW + h * PP + p0];
            float xB1 = g_xc[(size_t)tB * XBCW + h * PP + p0 + 1];
            g_y[(size_t)tA * IF + h * PP + p0]     = accD[nt][0] + e0 * off4[nt][0] + Dh * xA0;
            g_y[(size_t)tA * IF + h * PP + p0 + 1] = accD[nt][1] + e0 * off4[nt][1] + Dh * xA1;
            g_y[(size_t)tB * IF + h * PP + p0]     = accD[nt][2] + e1 * off4[nt][2] + Dh * xB0;
            g_y[(size_t)tB * IF + h * PP + p0 + 1] = accD[nt][3] + e1 * off4[nt][3] + Dh * xB1;
        }
    }
}

// ---------------- gated RMSNorm (float4 in, fp16 out) ----------------
__global__ __launch_bounds__(128) void gnorm_kernel(const float* __restrict__ nw) {
    int t = blockIdx.x;
    int tid = threadIdx.x;
    float4 v[3];
    float ss = 0.f;
#pragma unroll
    for (int k = 0; k < 3; k++) {
        int i = (tid + k * 128) * 4;
        float4 y = *reinterpret_cast<const float4*>(&g_y[(size_t)t * IF + i]);
        float4 z = *reinterpret_cast<const float4*>(&g_zx[(size_t)t * NPROJ + i]);
        float x0 = y.x * (z.x / (1.f + expf(-z.x)));
        float x1 = y.y * (z.y / (1.f + expf(-z.y)));
        float x2 = y.z * (z.z / (1.f + expf(-z.z)));
        float x3 = y.w * (z.w / (1.f + expf(-z.w)));
        v[k] = make_float4(x0, x1, x2, x3);
        ss += x0 * x0 + x1 * x1 + x2 * x2 + x3 * x3;
    }
    __shared__ float red[128];
    __shared__ float s_scale;
    red[tid] = ss;
    __syncthreads();
    for (int o = 64; o > 0; o >>= 1) {
        if (tid < o) red[tid] += red[tid + o];
        __syncthreads();
    }
    if (tid == 0) s_scale = rsqrtf(red[0] / (float)IF + 1e-5f);
    __syncthreads();
    float sc = s_scale;
#pragma unroll
    for (int k = 0; k < 3; k++) {
        int i = (tid + k * 128) * 4;
        float4 w = *reinterpret_cast<const float4*>(&nw[i]);
        __half2 h0 = __floats2half2_rn(v[k].x * sc * w.x, v[k].y * sc * w.y);
        __half2 h1 = __floats2half2_rn(v[k].z * sc * w.z, v[k].w * sc * w.w);
        *reinterpret_cast<__half2*>(&g_yh[(size_t)t * IF + i])     = h0;
        *reinterpret_cast<__half2*>(&g_yh[(size_t)t * IF + i + 2]) = h1;
    }
}

// ---------------- host launcher ----------------
extern "C" void kernel_launch(void* const* d_in, const int* in_sizes, int n_in,
                              void* d_out, int out_size) {
    const float* hs   = (const float*)d_in[0];
    const float* inw  = (const float*)d_in[1];
    const float* cw   = (const float*)d_in[2];
    const float* cb   = (const float*)d_in[3];
    const float* dtb  = (const float*)d_in[4];
    const float* alog = (const float*)d_in[5];
    const float* Dp   = (const float*)d_in[6];
    const float* nw   = (const float*)d_in[7];
    const float* ow   = (const float*)d_in[8];
    float* out = (float*)d_out;

    void *p_zx = nullptr, *p_yh = nullptr, *p_hsh = nullptr, *p_inwT = nullptr, *p_owT = nullptr;
    cudaGetSymbolAddress(&p_zx, g_zx);
    cudaGetSymbolAddress(&p_yh, g_yh);
    cudaGetSymbolAddress(&p_hsh, g_hsh);
    cudaGetSymbolAddress(&p_inwT, g_inwT);
    cudaGetSymbolAddress(&p_owT, g_owT);

    int smem_gemm = NSTAGE * 2 * STAGE_H * 2;                 // 61440
    int smem_cs = (64 * CS_SH + 128 * CS_SH) * 2;             // 27648
    int smem_y  = YD_HALves * 2 + 128 * 4;                    // ~53.8KB
    cudaFuncSetAttribute(f16gemm_kernel, cudaFuncAttributeMaxDynamicSharedMemorySize, smem_gemm);
    cudaFuncSetAttribute(chunkstate_mma_kernel, cudaFuncAttributeMaxDynamicSharedMemorySize, smem_cs);
    cudaFuncSetAttribute(ydiag_mma_kernel, cudaFuncAttributeMaxDynamicSharedMemorySize, smem_y);

    // 0. prep
    round_h_kernel<<<(TTOT * HIDD + 255) / 256, 256>>>(hs, (__half*)p_hsh, TTOT * HIDD);
    {
        dim3 g((NPROJ + 31) / 32, (HIDD + 31) / 32);
        transpose_round_h_kernel<<<g, dim3(32, 8)>>>(inw, (__half*)p_inwT, HIDD, NPROJ);
    }
    {
        dim3 g((HIDD + 31) / 32, (IF + 31) / 32);
        transpose_round_h_kernel<<<g, dim3(32, 8)>>>(ow, (__half*)p_owT, IF, HIDD);
    }

    // 1. in_proj GEMM (fp16)
    {
        dim3 grid((NPROJ + 127) / 128, TTOT / 128);
        f16gemm_kernel<<<grid, 256, smem_gemm>>>((const __half*)p_hsh, (const __half*)p_inwT,
                                                 (float*)p_zx, TTOT, NPROJ, HIDD);
    }
    // 2. conv + silu
    {
        dim3 grid(2, TTOT);
        conv_kernel<<<grid, 224>>>(cw, cb);
    }
    // 3. dt softplus
    dt_kernel<<<(TTOT * HH + 255) / 256, 256>>>(dtb);
    // 4. per-chunk cumsum
    acum_kernel<<<BSZ * HH * CN, 256>>>(alog);
    // 5. local chunk states (fp16 mma)
    chunkstate_mma_kernel<<<BSZ * CN * HH, 256, smem_cs>>>();
    // 6. inter-chunk recurrence
    recur_kernel<<<BSZ * HH * 32, 256>>>();
    // 7. Y (fp16 mma)
    {
        dim3 grid(4, BSZ * CN * HH);
        ydiag_mma_kernel<<<grid, 256, smem_y>>>(Dp);
    }
    // 8. gated RMSNorm (fp16 out)
    gnorm_kernel<<<TTOT, 128>>>(nw);
    // 9. out_proj GEMM (fp16)
    {
        dim3 grid(HIDD / 128, TTOT / 128);
        f16gemm_kernel<<<grid, 256, smem_gemm>>>((const __half*)p_yh, (const __half*)p_owT,
                                                 out, TTOT, HIDD, IF);
    }
}